// round 13
// baseline (speedup 1.0000x reference)
#include <cuda_runtime.h>
#include <cuda_bf16.h>
#include <cstdint>
#include <cstdio>

// Problem constants
#define BATCH 32
#define SEQ   512
#define DIM   512
#define HEADS 8
#define DK    64
#define FF    200
#define MTOT  (BATCH*SEQ)        // 16384
#define SD    (SEQ*DIM)          // 262144
#define QKN   (3*DIM)            // 1536 fused QKV width
#define LN_EPS 1e-5f
#define QSCALE (0.125f * 1.44269504088896340736f)   // 1/8 * log2(e)

// ---------------- scratch (device globals; no allocation allowed) -------------
__device__ float g_y0[MTOT*DIM];
__device__ float g_z [MTOT*DIM];
__device__ float g_psumA[BATCH*16];   // GEMM-emitted LN partials (16/batch)
__device__ float g_psqA [BATCH*16];
__device__ float g_psumB[BATCH*64];   // y2-stats partials (64/batch)
__device__ float g_psqB [BATCH*64];
__device__ float g_bqkv[QKN];

__device__ __nv_bfloat16 gb_x [MTOT*DIM];
__device__ __nv_bfloat16 gb_q [MTOT*DIM];
__device__ __nv_bfloat16 gb_k [MTOT*DIM];
__device__ __nv_bfloat16 gb_v [MTOT*DIM];
__device__ __nv_bfloat16 gb_cc[MTOT*DIM];
__device__ __nv_bfloat16 gb_y1[MTOT*DIM];
__device__ __nv_bfloat16 gb_f1[MTOT*FF];
__device__ __nv_bfloat16 gb_f2[MTOT*FF];
__device__ __nv_bfloat16 gb_wqkv[QKN*DIM];
__device__ __nv_bfloat16 gb_wo[DIM*DIM];
__device__ __nv_bfloat16 gb_w1[FF*DIM];
__device__ __nv_bfloat16 gb_w2[FF*FF];
__device__ __nv_bfloat16 gb_w3[DIM*FF];

// ---------------- helpers ------------------------------------------------------
__device__ __forceinline__ uint32_t pack_bf16(float a, float b) {
    __nv_bfloat162 h = __floats2bfloat162_rn(a, b);
    return *(uint32_t*)&h;
}

__device__ __forceinline__ float fexp2(float x) {
    float y;
    asm("ex2.approx.ftz.f32 %0, %1;" : "=f"(y) : "f"(x));
    return y;
}

// deterministic 16-partial LN reduce (fixed sequential order)
__device__ __forceinline__ void ln_from16(const float* ps, const float* pq, int b,
                                          float& m, float& r) {
    float s = 0.f, q = 0.f;
    #pragma unroll
    for (int t = 0; t < 16; t++) { s += ps[b*16 + t]; q += pq[b*16 + t]; }
    m = s / (float)SD;
    r = rsqrtf(q / (float)SD - m * m + LN_EPS);
}

__device__ __forceinline__ void mma_bf16(float* c, const uint32_t* a, const uint32_t* b) {
    asm volatile(
        "mma.sync.aligned.m16n8k16.row.col.f32.bf16.bf16.f32 "
        "{%0,%1,%2,%3}, {%4,%5,%6,%7}, {%8,%9}, {%0,%1,%2,%3};\n"
        : "+f"(c[0]), "+f"(c[1]), "+f"(c[2]), "+f"(c[3])
        : "r"(a[0]), "r"(a[1]), "r"(a[2]), "r"(a[3]),
          "r"(b[0]), "r"(b[1]));
}

__device__ __forceinline__ void ldmatrix_x4(uint32_t* r, const void* p) {
    uint32_t a = (uint32_t)__cvta_generic_to_shared(p);
    asm volatile("ldmatrix.sync.aligned.m8n8.x4.shared.b16 {%0,%1,%2,%3}, [%4];"
                 : "=r"(r[0]), "=r"(r[1]), "=r"(r[2]), "=r"(r[3]) : "r"(a));
}
__device__ __forceinline__ void ldmatrix_x2(uint32_t* r, const void* p) {
    uint32_t a = (uint32_t)__cvta_generic_to_shared(p);
    asm volatile("ldmatrix.sync.aligned.m8n8.x2.shared.b16 {%0,%1}, [%2];"
                 : "=r"(r[0]), "=r"(r[1]) : "r"(a));
}
__device__ __forceinline__ void ldmatrix_x2t(uint32_t* r, const void* p) {
    uint32_t a = (uint32_t)__cvta_generic_to_shared(p);
    asm volatile("ldmatrix.sync.aligned.m8n8.x2.trans.shared.b16 {%0,%1}, [%2];"
                 : "=r"(r[0]), "=r"(r[1]) : "r"(a));
}

__device__ __forceinline__ void cp_async16(void* smem, const void* gmem, bool valid) {
    uint32_t s = (uint32_t)__cvta_generic_to_shared(smem);
    int sz = valid ? 16 : 0;
    asm volatile("cp.async.cg.shared.global [%0], [%1], 16, %2;"
                 :: "r"(s), "l"(gmem), "r"(sz));
}
__device__ __forceinline__ void cp_commit() { asm volatile("cp.async.commit_group;"); }
__device__ __forceinline__ void cp_wait1()  { asm volatile("cp.async.wait_group 1;"); }

// ---------------- converts + bias build (single launch) ------------------------
struct CvtSeg  { const float* src; __nv_bfloat16* dst; int n4; float scale; };
struct CvtArgs { CvtSeg seg[8]; };

__global__ void cvt_multi(CvtArgs a, const float* __restrict__ bq,
                          const float* __restrict__ bk, const float* __restrict__ bv,
                          float* __restrict__ bqkv)
{
    const int gi = blockIdx.x * blockDim.x + threadIdx.x;
    if (gi < QKN) {
        float v;
        if (gi < DIM)        v = bq[gi] * QSCALE;
        else if (gi < 2*DIM) v = bk[gi - DIM];
        else                 v = bv[gi - 2*DIM];
        bqkv[gi] = v;
    }
    #pragma unroll
    for (int sg = 0; sg < 8; sg++) {
        const float* src = a.seg[sg].src;
        __nv_bfloat16* dst = a.seg[sg].dst;
        const int n4 = a.seg[sg].n4;
        const float sc = a.seg[sg].scale;
        for (int i = gi; i < n4; i += gridDim.x * blockDim.x) {
            float4 v = ((const float4*)src)[i];
            uint2 p;
            p.x = pack_bf16(v.x * sc, v.y * sc);
            p.y = pack_bf16(v.z * sc, v.w * sc);
            ((uint2*)dst)[i] = p;
        }
    }
}

// ---------------- BF16 GEMM: 128x128, BK=32, 2-stage cp.async ------------------
// optional fused LN partial stats (psum/psq, 16 slots/batch);
// optional on-the-fly LN residual from partials (lnx + lnps/lnpq):
//   res = (lnx - m1) * r1 * gamma + beta, m1/r1 reduced inline from 16 partials
#define GP 40
__global__ void __launch_bounds__(256)
gemm_bf16_kernel(const __nv_bfloat16* __restrict__ A, const __nv_bfloat16* __restrict__ B,
                 const float* __restrict__ bias, const float* __restrict__ res,
                 float* __restrict__ C, __nv_bfloat16* __restrict__ Cb,
                 int M, int N, int K, int relu,
                 float* __restrict__ psum, float* __restrict__ psq,
                 const float* __restrict__ lnx, const float* __restrict__ lngam,
                 const float* __restrict__ lnbet,
                 const float* __restrict__ lnps, const float* __restrict__ lnpq)
{
    __shared__ __nv_bfloat16 As[2][128][GP];
    __shared__ __nv_bfloat16 Bs[2][128][GP];
    __shared__ float sred[8], qred[8];
    __shared__ float s_m1, s_r1;

    const int tid  = threadIdx.x;
    const int wid  = tid >> 5;
    const int lane = tid & 31;
    const int wm   = wid >> 2;
    const int wn   = wid & 3;
    const int qr   = lane >> 2;
    const int qc   = lane & 3;
    const int m0   = blockIdx.y * 128;
    const int n0   = blockIdx.x * 128;

    const int lr  = tid >> 2;
    const int c8  = (tid & 3) * 8;

    const int l15 = lane & 15;
    const int a_co = (lane >> 4) << 3;
    const int l7  = lane & 7;
    const int b_co = ((lane >> 3) & 1) << 3;

    if (lnx && tid == 0) {
        float m1, r1;
        ln_from16(lnps, lnpq, m0 >> 9, m1, r1);
        s_m1 = m1; s_r1 = r1;
    }

    float acc[4][4][4];
    #pragma unroll
    for (int i = 0; i < 4; i++)
        #pragma unroll
        for (int j = 0; j < 4; j++)
            #pragma unroll
            for (int r = 0; r < 4; r++) acc[i][j][r] = 0.f;

    const int KT = (K + 31) >> 5;

    auto load_stage = [&](int st, int kt) {
        const int kc = kt * 32 + c8;
        const bool kok = (kc < K);
        #pragma unroll
        for (int half = 0; half < 2; half++) {
            const int r = lr + 64 * half;
            cp_async16(&As[st][r][c8], A + (size_t)(m0 + r) * K + kc, kok);
            const int n = n0 + r;
            cp_async16(&Bs[st][r][c8], B + (size_t)n * K + kc, kok && (n < N));
        }
    };

    load_stage(0, 0);
    cp_commit();

    for (int kt = 0; kt < KT; kt++) {
        if (kt + 1 < KT) load_stage((kt + 1) & 1, kt + 1);
        cp_commit();
        cp_wait1();
        __syncthreads();

        const int st = kt & 1;
        #pragma unroll
        for (int ks = 0; ks < 2; ks++) {
            uint32_t afr[4][4], bfr[4][2];
            #pragma unroll
            for (int i = 0; i < 4; i++)
                ldmatrix_x4(afr[i], &As[st][wm*64 + i*16 + l15][ks*16 + a_co]);
            #pragma unroll
            for (int j = 0; j < 4; j++)
                ldmatrix_x2(bfr[j], &Bs[st][wn*32 + j*8 + l7][ks*16 + b_co]);
            #pragma unroll
            for (int i = 0; i < 4; i++)
                #pragma unroll
                for (int j = 0; j < 4; j++)
                    mma_bf16(acc[i][j], afr[i], bfr[j]);
        }
        __syncthreads();
    }

    const float m1 = lnx ? s_m1 : 0.f;
    const float r1s = lnx ? s_r1 : 0.f;

    float ts = 0.f, tq = 0.f;
    #pragma unroll
    for (int i = 0; i < 4; i++) {
        const int row = m0 + wm * 64 + i * 16 + qr;
        #pragma unroll
        for (int j = 0; j < 4; j++) {
            const int col = n0 + wn * 32 + j * 8 + 2 * qc;
            if (col < N) {
                const float2 bi = *(const float2*)(bias + col);
                float v0 = acc[i][j][0] + bi.x;
                float v1 = acc[i][j][1] + bi.y;
                float v2 = acc[i][j][2] + bi.x;
                float v3 = acc[i][j][3] + bi.y;
                if (res) {
                    const float2 r0 = *(const float2*)(res + (size_t)row * N + col);
                    const float2 r1 = *(const float2*)(res + (size_t)(row + 8) * N + col);
                    v0 += r0.x; v1 += r0.y; v2 += r1.x; v3 += r1.y;
                }
                if (lnx) {
                    const int sr0 = row & 511, sr1 = (row + 8) & 511;
                    const float2 x0 = *(const float2*)(lnx + (size_t)row * N + col);
                    const float2 x1 = *(const float2*)(lnx + (size_t)(row + 8) * N + col);
                    const float2 g0 = *(const float2*)(lngam + (size_t)sr0 * N + col);
                    const float2 e0 = *(const float2*)(lnbet + (size_t)sr0 * N + col);
                    const float2 g1 = *(const float2*)(lngam + (size_t)sr1 * N + col);
                    const float2 e1 = *(const float2*)(lnbet + (size_t)sr1 * N + col);
                    v0 += (x0.x - m1) * r1s * g0.x + e0.x;
                    v1 += (x0.y - m1) * r1s * g0.y + e0.y;
                    v2 += (x1.x - m1) * r1s * g1.x + e1.x;
                    v3 += (x1.y - m1) * r1s * g1.y + e1.y;
                }
                if (relu) {
                    v0 = fmaxf(v0, 0.f); v1 = fmaxf(v1, 0.f);
                    v2 = fmaxf(v2, 0.f); v3 = fmaxf(v3, 0.f);
                }
                if (C) {
                    *(float2*)(C + (size_t)row * N + col)       = make_float2(v0, v1);
                    *(float2*)(C + (size_t)(row + 8) * N + col) = make_float2(v2, v3);
                }
                if (Cb) {
                    *(uint32_t*)(Cb + (size_t)row * N + col)       = pack_bf16(v0, v1);
                    *(uint32_t*)(Cb + (size_t)(row + 8) * N + col) = pack_bf16(v2, v3);
                }
                if (psum) {
                    ts += v0 + v1 + v2 + v3;
                    tq += v0*v0 + v1*v1 + v2*v2 + v3*v3;
                }
            }
        }
    }

    if (psum) {
        #pragma unroll
        for (int off = 16; off; off >>= 1) {
            ts += __shfl_xor_sync(0xffffffffu, ts, off);
            tq += __shfl_xor_sync(0xffffffffu, tq, off);
        }
        if (lane == 0) { sred[wid] = ts; qred[wid] = tq; }
        __syncthreads();
        if (tid == 0) {
            float S = 0.f, Q = 0.f;
            #pragma unroll
            for (int w = 0; w < 8; w++) { S += sred[w]; Q += qred[w]; }
            const int slot = (blockIdx.y >> 2) * 16 + (blockIdx.y & 3) * 4 + blockIdx.x;
            psum[slot] = S;
            psq [slot] = Q;
        }
    }
}

// QKV GEMM: A[M,512] x Wqkv[1536,512]^T; epilogue splits cols into q/k/v buffers
__global__ void __launch_bounds__(256)
gemm_qkv_kernel(const __nv_bfloat16* __restrict__ A, const __nv_bfloat16* __restrict__ B,
                const float* __restrict__ bias,
                __nv_bfloat16* __restrict__ Qo, __nv_bfloat16* __restrict__ Ko,
                __nv_bfloat16* __restrict__ Vo)
{
    __shared__ __nv_bfloat16 As[2][128][GP];
    __shared__ __nv_bfloat16 Bs[2][128][GP];

    const int tid  = threadIdx.x;
    const int wid  = tid >> 5;
    const int lane = tid & 31;
    const int wm   = wid >> 2;
    const int wn   = wid & 3;
    const int qr   = lane >> 2;
    const int qc   = lane & 3;
    const int m0   = blockIdx.y * 128;
    const int n0   = blockIdx.x * 128;
    const int K    = DIM;

    const int lr  = tid >> 2;
    const int c8  = (tid & 3) * 8;

    const int l15 = lane & 15;
    const int a_co = (lane >> 4) << 3;
    const int l7  = lane & 7;
    const int b_co = ((lane >> 3) & 1) << 3;

    float acc[4][4][4];
    #pragma unroll
    for (int i = 0; i < 4; i++)
        #pragma unroll
        for (int j = 0; j < 4; j++)
            #pragma unroll
            for (int r = 0; r < 4; r++) acc[i][j][r] = 0.f;

    const int KT = K >> 5;

    auto load_stage = [&](int st, int kt) {
        const int kc = kt * 32 + c8;
        #pragma unroll
        for (int half = 0; half < 2; half++) {
            const int r = lr + 64 * half;
            cp_async16(&As[st][r][c8], A + (size_t)(m0 + r) * K + kc, true);
            cp_async16(&Bs[st][r][c8], B + (size_t)(n0 + r) * K + kc, true);
        }
    };

    load_stage(0, 0);
    cp_commit();

    for (int kt = 0; kt < KT; kt++) {
        if (kt + 1 < KT) load_stage((kt + 1) & 1, kt + 1);
        cp_commit();
        cp_wait1();
        __syncthreads();

        const int st = kt & 1;
        #pragma unroll
        for (int ks = 0; ks < 2; ks++) {
            uint32_t afr[4][4], bfr[4][2];
            #pragma unroll
            for (int i = 0; i < 4; i++)
                ldmatrix_x4(afr[i], &As[st][wm*64 + i*16 + l15][ks*16 + a_co]);
            #pragma unroll
            for (int j = 0; j < 4; j++)
                ldmatrix_x2(bfr[j], &Bs[st][wn*32 + j*8 + l7][ks*16 + b_co]);
            #pragma unroll
            for (int i = 0; i < 4; i++)
                #pragma unroll
                for (int j = 0; j < 4; j++)
                    mma_bf16(acc[i][j], afr[i], bfr[j]);
        }
        __syncthreads();
    }

    #pragma unroll
    for (int i = 0; i < 4; i++) {
        const int row = m0 + wm * 64 + i * 16 + qr;
        #pragma unroll
        for (int j = 0; j < 4; j++) {
            const int col = n0 + wn * 32 + j * 8 + 2 * qc;
            const float2 bi = *(const float2*)(bias + col);
            float v0 = acc[i][j][0] + bi.x;
            float v1 = acc[i][j][1] + bi.y;
            float v2 = acc[i][j][2] + bi.x;
            float v3 = acc[i][j][3] + bi.y;
            __nv_bfloat16* dst = (col < DIM) ? Qo : (col < 2*DIM ? Ko : Vo);
            const int lc = col & (DIM - 1);
            *(uint32_t*)(dst + (size_t)row * DIM + lc)       = pack_bf16(v0, v1);
            *(uint32_t*)(dst + (size_t)(row + 8) * DIM + lc) = pack_bf16(v2, v3);
        }
    }
}

// ---------------- BF16 flash attention (R10, unchanged) ------------------------
#define APB 72
__global__ void __launch_bounds__(256)
attn_bf16_kernel(const __nv_bfloat16* __restrict__ Q, const __nv_bfloat16* __restrict__ K,
                 const __nv_bfloat16* __restrict__ V, __nv_bfloat16* __restrict__ O)
{
    extern __shared__ __nv_bfloat16 smb[];
    __nv_bfloat16* Qs = smb;                   // [128][APB]
    __nv_bfloat16* Ks = smb + 128*APB;         // [2][64][APB]
    __nv_bfloat16* Vs = Ks + 2*64*APB;         // [2][64][APB]

    const int tid  = threadIdx.x;
    const int w    = tid >> 5;
    const int lane = tid & 31;
    const int qr   = lane >> 2;
    const int qc   = lane & 3;
    const int bh   = blockIdx.y;
    const int b    = bh >> 3, h = bh & 7;
    const int q0   = blockIdx.x * 128;
    const __nv_bfloat16* Qp = Q + ((size_t)b * SEQ + q0) * DIM + h * DK;
    const __nv_bfloat16* Kp = K + ((size_t)b * SEQ) * DIM + h * DK;
    const __nv_bfloat16* Vp = V + ((size_t)b * SEQ) * DIM + h * DK;
    const int mb = w * 16;

    const int l15 = lane & 15;
    const int a_co = (lane >> 4) << 3;
    const int l7  = lane & 7;
    const int b_co = ((lane >> 3) & 1) << 3;

    #pragma unroll
    for (int it = 0; it < 4; it++) {
        const int idx = tid + 256 * it;
        const int r = idx >> 3, cc8 = (idx & 7) * 8;
        *(uint4*)&Qs[r*APB + cc8] = *(const uint4*)(Qp + (size_t)r * DIM + cc8);
    }

    const int kvr = tid >> 2;
    const int kvc = (tid & 3) * 16;
    auto load_kv = [&](int st, int kt) {
        const int t0 = kt * 64;
        const size_t gofs = (size_t)(t0 + kvr) * DIM;
        __nv_bfloat16* kd = Ks + (st*64 + kvr)*APB;
        __nv_bfloat16* vd = Vs + (st*64 + kvr)*APB;
        cp_async16(kd + kvc,     Kp + gofs + kvc,     true);
        cp_async16(kd + kvc + 8, Kp + gofs + kvc + 8, true);
        cp_async16(vd + kvc,     Vp + gofs + kvc,     true);
        cp_async16(vd + kvc + 8, Vp + gofs + kvc + 8, true);
    };
    load_kv(0, 0); cp_commit();

    __syncthreads();
    uint32_t qf[4][4];
    #pragma unroll
    for (int ks = 0; ks < 4; ks++)
        ldmatrix_x4(qf[ks], &Qs[(mb + l15)*APB + ks*16 + a_co]);

    float o[8][4];
    #pragma unroll
    for (int j = 0; j < 8; j++)
        #pragma unroll
        for (int r = 0; r < 4; r++) o[j][r] = 0.f;
    float rowm0 = -1e30f, rowm1 = -1e30f, rowl0 = 0.f, rowl1 = 0.f;

    const int NT = SEQ / 64;
    for (int kt = 0; kt < NT; kt++) {
        if (kt + 1 < NT) load_kv((kt + 1) & 1, kt + 1);
        cp_commit();
        cp_wait1();
        __syncthreads();
        const int st = kt & 1;

        float s[8][4];
        #pragma unroll
        for (int j = 0; j < 8; j++)
            #pragma unroll
            for (int r = 0; r < 4; r++) s[j][r] = 0.f;
        #pragma unroll
        for (int ks = 0; ks < 4; ks++) {
            #pragma unroll
            for (int j = 0; j < 8; j++) {
                uint32_t bf[2];
                ldmatrix_x2(bf, &Ks[(st*64 + j*8 + l7)*APB + ks*16 + b_co]);
                mma_bf16(s[j], qf[ks], bf);
            }
        }

        float mt0 = -1e30f, mt1 = -1e30f;
        #pragma unroll
        for (int j = 0; j < 8; j++) {
            mt0 = fmaxf(mt0, fmaxf(s[j][0], s[j][1]));
            mt1 = fmaxf(mt1, fmaxf(s[j][2], s[j][3]));
        }
        mt0 = fmaxf(mt0, __shfl_xor_sync(0xffffffffu, mt0, 1));
        mt0 = fmaxf(mt0, __shfl_xor_sync(0xffffffffu, mt0, 2));
        mt1 = fmaxf(mt1, __shfl_xor_sync(0xffffffffu, mt1, 1));
        mt1 = fmaxf(mt1, __shfl_xor_sync(0xffffffffu, mt1, 2));

        const float mn0 = fmaxf(rowm0, mt0), mn1 = fmaxf(rowm1, mt1);
        const float sc0 = fexp2(rowm0 - mn0), sc1 = fexp2(rowm1 - mn1);
        rowm0 = mn0; rowm1 = mn1;

        float ps0 = 0.f, ps1 = 0.f;
        #pragma unroll
        for (int j = 0; j < 8; j++) {
            s[j][0] = fexp2(s[j][0] - mn0);
            s[j][1] = fexp2(s[j][1] - mn0);
            s[j][2] = fexp2(s[j][2] - mn1);
            s[j][3] = fexp2(s[j][3] - mn1);
            ps0 += s[j][0] + s[j][1];
            ps1 += s[j][2] + s[j][3];
        }
        ps0 += __shfl_xor_sync(0xffffffffu, ps0, 1);
        ps0 += __shfl_xor_sync(0xffffffffu, ps0, 2);
        ps1 += __shfl_xor_sync(0xffffffffu, ps1, 1);
        ps1 += __shfl_xor_sync(0xffffffffu, ps1, 2);
        rowl0 = rowl0 * sc0 + ps0;
        rowl1 = rowl1 * sc1 + ps1;

        #pragma unroll
        for (int j = 0; j < 8; j++) {
            o[j][0] *= sc0; o[j][1] *= sc0;
            o[j][2] *= sc1; o[j][3] *= sc1;
        }

        #pragma unroll
        for (int kb = 0; kb < 4; kb++) {
            uint32_t a[4];
            a[0] = pack_bf16(s[2*kb  ][0], s[2*kb  ][1]);
            a[1] = pack_bf16(s[2*kb  ][2], s[2*kb  ][3]);
            a[2] = pack_bf16(s[2*kb+1][0], s[2*kb+1][1]);
            a[3] = pack_bf16(s[2*kb+1][2], s[2*kb+1][3]);
            #pragma unroll
            for (int j = 0; j < 8; j++) {
                uint32_t bf[2];
                ldmatrix_x2t(bf, &Vs[(st*64 + kb*16 + l15)*APB + j*8]);
                mma_bf16(o[j], a, bf);
            }
        }
        __syncthreads();
    }

    const float inv0 = 1.f / rowl0, inv1 = 1.f / rowl1;
    const int r0 = q0 + mb + qr, r1 = r0 + 8;
    #pragma unroll
    for (int j = 0; j < 8; j++) {
        const int col = h * DK + j * 8 + 2 * qc;
        *(uint32_t*)(O + ((size_t)b * SEQ + r0) * DIM + col) =
            pack_bf16(o[j][0] * inv0, o[j][1] * inv0);
        *(uint32_t*)(O + ((size_t)b * SEQ + r1) * DIM + col) =
            pack_bf16(o[j][2] * inv1, o[j][3] * inv1);
    }
}

// ---------------- LayerNorm kernels (tiny reducers inlined) --------------------
// LN1 apply -> bf16 only; m/r reduced inline from GEMM partials (32-batch table)
__global__ void ln_apply_bf16_kernel(const float* __restrict__ X,
                                     const float* __restrict__ gamma, const float* __restrict__ beta,
                                     const float* __restrict__ ps, const float* __restrict__ pq,
                                     __nv_bfloat16* __restrict__ Yb)
{
    __shared__ float sm_m[BATCH], sm_r[BATCH];
    if (threadIdx.x < BATCH) {
        float m, r;
        ln_from16(ps, pq, threadIdx.x, m, r);
        sm_m[threadIdx.x] = m; sm_r[threadIdx.x] = r;
    }
    __syncthreads();

    const float4* x4 = (const float4*)X;
    const float4* g4 = (const float4*)gamma;
    const float4* b4 = (const float4*)beta;
    const int total = BATCH * (SD/4);
    for (int idx = blockIdx.x * blockDim.x + threadIdx.x; idx < total;
         idx += gridDim.x * blockDim.x) {
        const int b   = idx >> 16;
        const int loc = idx & 65535;
        const float m = sm_m[b], r = sm_r[b];
        float4 v = x4[idx], g = g4[loc], be = b4[loc];
        uint2 p;
        p.x = pack_bf16((v.x - m) * r * g.x + be.x, (v.y - m) * r * g.y + be.y);
        p.y = pack_bf16((v.z - m) * r * g.z + be.z, (v.w - m) * r * g.w + be.w);
        ((uint2*)Yb)[idx] = p;
    }
}

// stats of y2 = LN2(z) on the fly; m2/r2 reduced inline from GEMM partials
__global__ void ln_stats_y2_kernel(const float* __restrict__ Z,
                                   const float* __restrict__ gamma, const float* __restrict__ beta,
                                   const float* __restrict__ psA, const float* __restrict__ pqA,
                                   float* __restrict__ psB, float* __restrict__ pqB)
{
    const int b = blockIdx.y, chunk = blockIdx.x;
    __shared__ float s_m2, s_r2;
    if (threadIdx.x == 0) {
        float m, r;
        ln_from16(psA, pqA, b, m, r);
        s_m2 = m; s_r2 = r;
    }
    __syncthreads();
    const float m = s_m2, r = s_r2;

    const size_t base = (size_t)b * SD + (size_t)chunk * 4096;
    const float4* z4 = (const float4*)(Z + base);
    const float4* g4 = (const float4*)(gamma + (size_t)chunk * 4096);
    const float4* b4 = (const float4*)(beta  + (size_t)chunk * 4096);
    float s = 0.f, q = 0.f;
    #pragma unroll
    for (int i = 0; i < 4; i++) {
        const int t = threadIdx.x + 256*i;
        float4 v = z4[t], g = g4[t], be = b4[t];
        float4 y;
        y.x = (v.x - m) * r * g.x + be.x;
        y.y = (v.y - m) * r * g.y + be.y;
        y.z = (v.z - m) * r * g.z + be.z;
        y.w = (v.w - m) * r * g.w + be.w;
        s += y.x + y.y + y.z + y.w;
        q += y.x*y.x + y.y*y.y + y.z*y.z + y.w*y.w;
    }
    #pragma unroll
    for (int off = 16; off; off >>= 1) {
        s += __shfl_down_sync(0xffffffffu, s, off);
        q += __shfl_down_sync(0xffffffffu, q, off);
    }
    __shared__ float ws[8], wq[8];
    if ((threadIdx.x & 31) == 0) { ws[threadIdx.x >> 5] = s; wq[threadIdx.x >> 5] = q; }
    __syncthreads();
    if (threadIdx.x == 0) {
        float S = 0.f, Q = 0.f;
        #pragma unroll
        for (int w = 0; w < 8; w++) { S += ws[w]; Q += wq[w]; }
        psB[b*64 + chunk] = S;
        pqB[b*64 + chunk] = Q;
    }
}

// out = LN3( LN2(z) ); all stats reduced inline (16 + 64 partials per batch)
__global__ void ln_apply_y2_kernel(const float* __restrict__ Z,
                                   const float* __restrict__ gamma, const float* __restrict__ beta,
                                   const float* __restrict__ psA, const float* __restrict__ pqA,
                                   const float* __restrict__ psB, const float* __restrict__ pqB,
                                   float* __restrict__ out)
{
    __shared__ float sm2[BATCH], sr2[BATCH], sm3[BATCH], sr3[BATCH];
    if (threadIdx.x < BATCH) {
        const int b = threadIdx.x;
        float m2, r2;
        ln_from16(psA, pqA, b, m2, r2);
        sm2[b] = m2; sr2[b] = r2;
        float s = 0.f, q = 0.f;
        #pragma unroll
        for (int t = 0; t < 64; t++) { s += psB[b*64 + t]; q += pqB[b*64 + t]; }
        const float m3 = s / (float)SD;
        sm3[b] = m3;
        sr3[b] = rsqrtf(q / (float)SD - m3 * m3 + LN_EPS);
    }
    __syncthreads();

    const float4* z4 = (const float4*)Z;
    const float4* g4 = (const float4*)gamma;
    const float4* b4 = (const float4*)beta;
    float4* o4 = (float4*)out;
    const int total = BATCH * (SD/4);
    for (int idx = blockIdx.x * blockDim.x + threadIdx.x; idx < total;
         idx += gridDim.x * blockDim.x) {
        const int b   = idx >> 16;
        const int loc = idx & 65535;
        const float m2 = sm2[b], r2 = sr2[b];
        const float m3 = sm3[b], r3 = sr3[b];
        float4 v = z4[idx], g = g4[loc], be = b4[loc];
        float4 y, o;
        y.x = (v.x - m2) * r2 * g.x + be.x;
        y.y = (v.y - m2) * r2 * g.y + be.y;
        y.z = (v.z - m2) * r2 * g.z + be.z;
        y.w = (v.w - m2) * r2 * g.w + be.w;
        o.x = (y.x - m3) * r3 * g.x + be.x;
        o.y = (y.y - m3) * r3 * g.y + be.y;
        o.z = (y.z - m3) * r3 * g.z + be.z;
        o.w = (y.w - m3) * r3 * g.w + be.w;
        o4[idx] = o;
    }
}

// ---------------- launch ------------------------------------------------------
#define ATTN_SMEM ((128*APB + 4*64*APB) * 2)   // 55296 bytes

extern "C" void kernel_launch(void* const* d_in, const int* in_sizes, int n_in,
                              void* d_out, int out_size)
{
    const float* x     = (const float*)d_in[0];
    const float* Wq    = (const float*)d_in[1];
    const float* bq    = (const float*)d_in[2];
    const float* Wk    = (const float*)d_in[3];
    const float* bk    = (const float*)d_in[4];
    const float* Wv    = (const float*)d_in[5];
    const float* bv    = (const float*)d_in[6];
    const float* Wo    = (const float*)d_in[7];
    const float* bo    = (const float*)d_in[8];
    const float* W1    = (const float*)d_in[9];
    const float* b1    = (const float*)d_in[10];
    const float* W2    = (const float*)d_in[11];
    const float* b2    = (const float*)d_in[12];
    const float* W3    = (const float*)d_in[13];
    const float* b3    = (const float*)d_in[14];
    const float* gamma = (const float*)d_in[15];
    const float* beta  = (const float*)d_in[16];
    float* out = (float*)d_out;

    float *y0_, *z_, *psA_, *pqA_, *psA2_, *pqA2_, *psB_, *pqB_, *bqkv_;
    cudaGetSymbolAddress((void**)&y0_, g_y0);
    cudaGetSymbolAddress((void**)&z_,  g_z);
    cudaGetSymbolAddress((void**)&psA_, g_psumA);
    cudaGetSymbolAddress((void**)&pqA_, g_psqA);
    cudaGetSymbolAddress((void**)&psB_, g_psumB);
    cudaGetSymbolAddress((void**)&pqB_, g_psqB);
    cudaGetSymbolAddress((void**)&bqkv_, g_bqkv);
    // second set of 16-partials for LN2 (reuse tail of psumB region? no — separate):
    psA2_ = psB_ + BATCH*64 - BATCH*16;  // careful: overlaps psB tail
    // Avoid overlap: allocate via distinct offsets inside g_psumB is wrong.
    // Use dedicated storage instead:
    static_assert(true, "");

    __nv_bfloat16 *xb, *qb, *kb, *vb, *ccb, *y1b, *f1b, *f2b;
    __nv_bfloat16 *wqkvb, *wob, *w1b, *w2b, *w3b;
    cudaGetSymbolAddress((void**)&xb,    gb_x);
    cudaGetSymbolAddress((void**)&qb,    gb_q);
    cudaGetSymbolAddress((void**)&kb,    gb_k);
    cudaGetSymbolAddress((void**)&vb,    gb_v);
    cudaGetSymbolAddress((void**)&ccb,   gb_cc);
    cudaGetSymbolAddress((void**)&y1b,   gb_y1);
    cudaGetSymbolAddress((void**)&f1b,   gb_f1);
    cudaGetSymbolAddress((void**)&f2b,   gb_f2);
    cudaGetSymbolAddress((void**)&wqkvb, gb_wqkv);
    cudaGetSymbolAddress((void**)&wob,   gb_wo);
    cudaGetSymbolAddress((void**)&w1b,   gb_w1);
    cudaGetSymbolAddress((void**)&w2b,   gb_w2);
    cudaGetSymbolAddress((void**)&w3b,   gb_w3);

    cudaFuncSetAttribute(attn_bf16_kernel,
                         cudaFuncAttributeMaxDynamicSharedMemorySize, ATTN_SMEM);

    // converts + bias build in ONE launch; Wq pre-scaled by (1/8)*log2(e)
    CvtArgs ca;
    ca.seg[0] = { x,  xb,                  (MTOT*DIM)/4, 1.f    };
    ca.seg[1] = { Wq, wqkvb,               (DIM*DIM)/4,  QSCALE };
    ca.seg[2] = { Wk, wqkvb + DIM*DIM,     (DIM*DIM)/4,  1.f    };
    ca.seg[3] = { Wv, wqkvb + 2*DIM*DIM,   (DIM*DIM)/4,  1.f    };
    ca.seg[4] = { Wo, wob,                 (DIM*DIM)/4,  1.f    };
    ca.seg[5] = { W1, w1b,                 (FF*DIM)/4,   1.f    };
    ca.seg[6] = { W2, w2b,                 (FF*FF)/4,    1.f    };
    ca.seg[7] = { W3, w3b,                 (DIM*FF)/4,   1.f    };
    cvt_multi<<<1024, 256>>>(ca, bq, bk, bv, bqkv_);

    // fused QKV projection, split outputs
    gemm_qkv_kernel<<<dim3(12, 128), 256>>>(xb, wqkvb, bqkv_, qb, kb, vb);

    // attention (128 q-rows per block)
    attn_bf16_kernel<<<dim3(SEQ/128, BATCH*HEADS), 256, ATTN_SMEM>>>(qb, kb, vb, ccb);

    // output projection + bias + residual(x) -> fp32 y0, fused LN1 partial stats (psA)
    gemm_bf16_kernel<<<dim3(4, 128), 256>>>(ccb, wob, bo, x, y0_, nullptr,
                                            MTOT, DIM, DIM, 0, psA_, pqA_,
                                            nullptr, nullptr, nullptr, nullptr, nullptr);

    // LN1 apply -> y1b (m1/r1 reduced inline from psA)
    ln_apply_bf16_kernel<<<2048, 256>>>(y0_, gamma, beta, psA_, pqA_, y1b);

    // FFN
    gemm_bf16_kernel<<<dim3(2, 128), 256>>>(y1b, w1b, b1, nullptr, nullptr, f1b,
                                            MTOT, FF, DIM, 1, nullptr, nullptr,
                                            nullptr, nullptr, nullptr, nullptr, nullptr);
    gemm_bf16_kernel<<<dim3(2, 128), 256>>>(f1b, w2b, b2, nullptr, nullptr, f2b,
                                            MTOT, FF, FF, 1, nullptr, nullptr,
                                            nullptr, nullptr, nullptr, nullptr, nullptr);
    // W3: y1 recomputed inline from y0 + psA partials; emits LN2 partials -> psB[0:512]
    // (psB 16-slot region: reuse first BATCH*16 of psumB? NO - y2 stats need 64/batch.
    //  LN2 partials go to psA (overwrite after last use? psA still needed by W3 itself
    //  -> W3 reads psA at start, writes its own stats to a DIFFERT region: use
    //  psB's first BATCH*16 floats BEFORE y2-stats? y2-stats uses all 64/batch.
    //  Solution: W3 writes LN2 partials into psA2 = psB + no... use dedicated g_bqkv? too small.
    //  Simplest: W3 writes to psA after reading it (read happens at kernel start,
    //  write at kernel end -> same kernel, ordered within each block; but OTHER blocks
    //  may read psA after this block wrote. All blocks read psA only in their prologue;
    //  grid may overlap arbitrarily. UNSAFE. Use psB's last BATCH*16 floats?
    //  psB is BATCH*64; y2 stats fill all of it. CONFLICT.
    //  -> carve LN2 partials from psumB by extending: use pqA (LN1 sq partials) is
    //  ALSO still read by W3 prologue. Need fresh storage: reuse g_bqkv? 1536 floats
    //  >= 512+512. bqkv consumed by QKV GEMM only (long done). SAFE and deterministic.)
    gemm_bf16_kernel<<<dim3(4, 128), 256>>>(f2b, w3b, b3, nullptr, z_, nullptr,
                                            MTOT, DIM, FF, 0, bqkv_, bqkv_ + BATCH*16,
                                            y0_, gamma, beta, psA_, pqA_);

    // y2 stats (m2/r2 inlined from LN2 partials in bqkv) -> psB/pqB (64/batch)
    ln_stats_y2_kernel<<<dim3(64, BATCH), 256>>>(z_, gamma, beta,
                                                 bqkv_, bqkv_ + BATCH*16, psB_, pqB_);

    // final: LN3(LN2(z)) -> out, all stats inlined
    ln_apply_y2_kernel<<<2048, 256>>>(z_, gamma, beta,
                                      bqkv_, bqkv_ + BATCH*16, psB_, pqB_, out);
}

// round 14
// speedup vs baseline: 1.0581x; 1.0581x over previous
#include <cuda_runtime.h>
#include <cuda_bf16.h>
#include <cstdint>
#include <cstdio>

// Problem constants
#define BATCH 32
#define SEQ   512
#define DIM   512
#define HEADS 8
#define DK    64
#define FF    200
#define MTOT  (BATCH*SEQ)        // 16384
#define SD    (SEQ*DIM)          // 262144
#define QKN   (3*DIM)            // 1536 fused QKV width
#define LN_EPS 1e-5f
#define QSCALE (0.125f * 1.44269504088896340736f)   // 1/8 * log2(e)

// ---------------- scratch (device globals; no allocation allowed) -------------
__device__ float g_y0[MTOT*DIM];
__device__ float g_z [MTOT*DIM];
__device__ float g_psum[BATCH*64];
__device__ float g_psq [BATCH*64];
__device__ float g_mean[3*BATCH];
__device__ float g_rstd[3*BATCH];
__device__ float g_bqkv[QKN];

__device__ __nv_bfloat16 gb_x [MTOT*DIM];
__device__ __nv_bfloat16 gb_q [MTOT*DIM];
__device__ __nv_bfloat16 gb_k [MTOT*DIM];
__device__ __nv_bfloat16 gb_v [MTOT*DIM];
__device__ __nv_bfloat16 gb_cc[MTOT*DIM];
__device__ __nv_bfloat16 gb_y1[MTOT*DIM];
__device__ __nv_bfloat16 gb_f1[MTOT*FF];
__device__ __nv_bfloat16 gb_f2[MTOT*FF];
__device__ __nv_bfloat16 gb_wqkv[QKN*DIM];
__device__ __nv_bfloat16 gb_wo[DIM*DIM];
__device__ __nv_bfloat16 gb_w1[FF*DIM];
__device__ __nv_bfloat16 gb_w2[FF*FF];
__device__ __nv_bfloat16 gb_w3[DIM*FF];

// ---------------- helpers ------------------------------------------------------
__device__ __forceinline__ uint32_t pack_bf16(float a, float b) {
    __nv_bfloat162 h = __floats2bfloat162_rn(a, b);
    return *(uint32_t*)&h;
}

__device__ __forceinline__ float fexp2(float x) {
    float y;
    asm("ex2.approx.ftz.f32 %0, %1;" : "=f"(y) : "f"(x));
    return y;
}

__device__ __forceinline__ void mma_bf16(float* c, const uint32_t* a, const uint32_t* b) {
    asm volatile(
        "mma.sync.aligned.m16n8k16.row.col.f32.bf16.bf16.f32 "
        "{%0,%1,%2,%3}, {%4,%5,%6,%7}, {%8,%9}, {%0,%1,%2,%3};\n"
        : "+f"(c[0]), "+f"(c[1]), "+f"(c[2]), "+f"(c[3])
        : "r"(a[0]), "r"(a[1]), "r"(a[2]), "r"(a[3]),
          "r"(b[0]), "r"(b[1]));
}

__device__ __forceinline__ void ldmatrix_x4(uint32_t* r, const void* p) {
    uint32_t a = (uint32_t)__cvta_generic_to_shared(p);
    asm volatile("ldmatrix.sync.aligned.m8n8.x4.shared.b16 {%0,%1,%2,%3}, [%4];"
                 : "=r"(r[0]), "=r"(r[1]), "=r"(r[2]), "=r"(r[3]) : "r"(a));
}
__device__ __forceinline__ void ldmatrix_x2(uint32_t* r, const void* p) {
    uint32_t a = (uint32_t)__cvta_generic_to_shared(p);
    asm volatile("ldmatrix.sync.aligned.m8n8.x2.shared.b16 {%0,%1}, [%2];"
                 : "=r"(r[0]), "=r"(r[1]) : "r"(a));
}
__device__ __forceinline__ void ldmatrix_x2t(uint32_t* r, const void* p) {
    uint32_t a = (uint32_t)__cvta_generic_to_shared(p);
    asm volatile("ldmatrix.sync.aligned.m8n8.x2.trans.shared.b16 {%0,%1}, [%2];"
                 : "=r"(r[0]), "=r"(r[1]) : "r"(a));
}

__device__ __forceinline__ void cp_async16(void* smem, const void* gmem, bool valid) {
    uint32_t s = (uint32_t)__cvta_generic_to_shared(smem);
    int sz = valid ? 16 : 0;
    asm volatile("cp.async.cg.shared.global [%0], [%1], 16, %2;"
                 :: "r"(s), "l"(gmem), "r"(sz));
}
__device__ __forceinline__ void cp_commit() { asm volatile("cp.async.commit_group;"); }
__device__ __forceinline__ void cp_wait1()  { asm volatile("cp.async.wait_group 1;"); }

// ---------------- converts (single launch) -------------------------------------
struct CvtSeg  { const float* src; __nv_bfloat16* dst; int n4; float scale; };
struct CvtArgs { CvtSeg seg[8]; };

__global__ void cvt_multi(CvtArgs a)
{
    #pragma unroll
    for (int sg = 0; sg < 8; sg++) {
        const float* src = a.seg[sg].src;
        __nv_bfloat16* dst = a.seg[sg].dst;
        const int n4 = a.seg[sg].n4;
        const float sc = a.seg[sg].scale;
        for (int i = blockIdx.x * blockDim.x + threadIdx.x; i < n4;
             i += gridDim.x * blockDim.x) {
            float4 v = ((const float4*)src)[i];
            uint2 p;
            p.x = pack_bf16(v.x * sc, v.y * sc);
            p.y = pack_bf16(v.z * sc, v.w * sc);
            ((uint2*)dst)[i] = p;
        }
    }
}

__global__ void build_bias_qkv(const float* __restrict__ bq, const float* __restrict__ bk,
                               const float* __restrict__ bv, float* __restrict__ dst)
{
    int i = blockIdx.x * blockDim.x + threadIdx.x;
    if (i < QKN) {
        float v;
        if (i < DIM)            v = bq[i] * QSCALE;
        else if (i < 2*DIM)     v = bk[i - DIM];
        else                    v = bv[i - 2*DIM];
        dst[i] = v;
    }
}

// ---------------- BF16 GEMM: 128x128, BK=32, 3-stage cp.async ------------------
// single __syncthreads per k-tile; 2-deep prefetch
#define GP 40
__global__ void __launch_bounds__(256)
gemm_bf16_kernel(const __nv_bfloat16* __restrict__ A, const __nv_bfloat16* __restrict__ B,
                 const float* __restrict__ bias, const float* __restrict__ res,
                 float* __restrict__ C, __nv_bfloat16* __restrict__ Cb,
                 int M, int N, int K, int relu,
                 float* __restrict__ psum, float* __restrict__ psq,
                 const float* __restrict__ lnx, const float* __restrict__ lngam,
                 const float* __restrict__ lnbet, const float* __restrict__ lnmean,
                 const float* __restrict__ lnrstd)
{
    __shared__ __nv_bfloat16 As[3][128][GP];
    __shared__ __nv_bfloat16 Bs[3][128][GP];
    __shared__ float sred[8], qred[8];

    const int tid  = threadIdx.x;
    const int wid  = tid >> 5;
    const int lane = tid & 31;
    const int wm   = wid >> 2;
    const int wn   = wid & 3;
    const int qr   = lane >> 2;
    const int qc   = lane & 3;
    const int m0   = blockIdx.y * 128;
    const int n0   = blockIdx.x * 128;

    const int lr  = tid >> 2;
    const int c8  = (tid & 3) * 8;

    const int l15 = lane & 15;
    const int a_co = (lane >> 4) << 3;
    const int l7  = lane & 7;
    const int b_co = ((lane >> 3) & 1) << 3;

    float acc[4][4][4];
    #pragma unroll
    for (int i = 0; i < 4; i++)
        #pragma unroll
        for (int j = 0; j < 4; j++)
            #pragma unroll
            for (int r = 0; r < 4; r++) acc[i][j][r] = 0.f;

    const int KT = (K + 31) >> 5;

    auto load_stage = [&](int st, int kt) {
        const int kc = kt * 32 + c8;
        const bool kok = (kc < K);
        #pragma unroll
        for (int half = 0; half < 2; half++) {
            const int r = lr + 64 * half;
            cp_async16(&As[st][r][c8], A + (size_t)(m0 + r) * K + kc, kok);
            const int n = n0 + r;
            cp_async16(&Bs[st][r][c8], B + (size_t)n * K + kc, kok && (n < N));
        }
    };

    load_stage(0, 0);
    cp_commit();
    if (KT > 1) load_stage(1, 1);
    cp_commit();

    for (int kt = 0; kt < KT; kt++) {
        cp_wait1();               // tile kt resident (≤1 younger group pending)
        __syncthreads();          // all reads of stage (kt-1)%3 complete
        if (kt + 2 < KT) load_stage((kt + 2) % 3, kt + 2);
        cp_commit();

        const int st = kt % 3;
        #pragma unroll
        for (int ks = 0; ks < 2; ks++) {
            uint32_t afr[4][4], bfr[4][2];
            #pragma unroll
            for (int i = 0; i < 4; i++)
                ldmatrix_x4(afr[i], &As[st][wm*64 + i*16 + l15][ks*16 + a_co]);
            #pragma unroll
            for (int j = 0; j < 4; j++)
                ldmatrix_x2(bfr[j], &Bs[st][wn*32 + j*8 + l7][ks*16 + b_co]);
            #pragma unroll
            for (int i = 0; i < 4; i++)
                #pragma unroll
                for (int j = 0; j < 4; j++)
                    mma_bf16(acc[i][j], afr[i], bfr[j]);
        }
    }

    float ts = 0.f, tq = 0.f;
    #pragma unroll
    for (int i = 0; i < 4; i++) {
        const int row = m0 + wm * 64 + i * 16 + qr;
        #pragma unroll
        for (int j = 0; j < 4; j++) {
            const int col = n0 + wn * 32 + j * 8 + 2 * qc;
            if (col < N) {
                const float2 bi = *(const float2*)(bias + col);
                float v0 = acc[i][j][0] + bi.x;
                float v1 = acc[i][j][1] + bi.y;
                float v2 = acc[i][j][2] + bi.x;
                float v3 = acc[i][j][3] + bi.y;
                if (res) {
                    const float2 r0 = *(const float2*)(res + (size_t)row * N + col);
                    const float2 r1 = *(const float2*)(res + (size_t)(row + 8) * N + col);
                    v0 += r0.x; v1 += r0.y; v2 += r1.x; v3 += r1.y;
                }
                if (lnx) {
                    const int bidx = row >> 9;
                    const float m1 = lnmean[bidx], r1s = lnrstd[bidx];
                    const int sr0 = row & 511, sr1 = (row + 8) & 511;
                    const float2 x0 = *(const float2*)(lnx + (size_t)row * N + col);
                    const float2 x1 = *(const float2*)(lnx + (size_t)(row + 8) * N + col);
                    const float2 g0 = *(const float2*)(lngam + (size_t)sr0 * N + col);
                    const float2 e0 = *(const float2*)(lnbet + (size_t)sr0 * N + col);
                    const float2 g1 = *(const float2*)(lngam + (size_t)sr1 * N + col);
                    const float2 e1 = *(const float2*)(lnbet + (size_t)sr1 * N + col);
                    v0 += (x0.x - m1) * r1s * g0.x + e0.x;
                    v1 += (x0.y - m1) * r1s * g0.y + e0.y;
                    v2 += (x1.x - m1) * r1s * g1.x + e1.x;
                    v3 += (x1.y - m1) * r1s * g1.y + e1.y;
                }
                if (relu) {
                    v0 = fmaxf(v0, 0.f); v1 = fmaxf(v1, 0.f);
                    v2 = fmaxf(v2, 0.f); v3 = fmaxf(v3, 0.f);
                }
                if (C) {
                    *(float2*)(C + (size_t)row * N + col)       = make_float2(v0, v1);
                    *(float2*)(C + (size_t)(row + 8) * N + col) = make_float2(v2, v3);
                }
                if (Cb) {
                    *(uint32_t*)(Cb + (size_t)row * N + col)       = pack_bf16(v0, v1);
                    *(uint32_t*)(Cb + (size_t)(row + 8) * N + col) = pack_bf16(v2, v3);
                }
                if (psum) {
                    ts += v0 + v1 + v2 + v3;
                    tq += v0*v0 + v1*v1 + v2*v2 + v3*v3;
                }
            }
        }
    }

    if (psum) {
        #pragma unroll
        for (int off = 16; off; off >>= 1) {
            ts += __shfl_xor_sync(0xffffffffu, ts, off);
            tq += __shfl_xor_sync(0xffffffffu, tq, off);
        }
        if (lane == 0) { sred[wid] = ts; qred[wid] = tq; }
        __syncthreads();
        if (tid == 0) {
            float S = 0.f, Q = 0.f;
            #pragma unroll
            for (int w = 0; w < 8; w++) { S += sred[w]; Q += qred[w]; }
            const int slot = (blockIdx.y >> 2) * 16 + (blockIdx.y & 3) * 4 + blockIdx.x;
            psum[slot] = S;
            psq [slot] = Q;
        }
    }
}

// QKV GEMM: A[M,512] x Wqkv[1536,512]^T; 3-stage pipe; split q/k/v epilogue
__global__ void __launch_bounds__(256)
gemm_qkv_kernel(const __nv_bfloat16* __restrict__ A, const __nv_bfloat16* __restrict__ B,
                const float* __restrict__ bias,
                __nv_bfloat16* __restrict__ Qo, __nv_bfloat16* __restrict__ Ko,
                __nv_bfloat16* __restrict__ Vo)
{
    __shared__ __nv_bfloat16 As[3][128][GP];
    __shared__ __nv_bfloat16 Bs[3][128][GP];

    const int tid  = threadIdx.x;
    const int wid  = tid >> 5;
    const int lane = tid & 31;
    const int wm   = wid >> 2;
    const int wn   = wid & 3;
    const int qr   = lane >> 2;
    const int qc   = lane & 3;
    const int m0   = blockIdx.y * 128;
    const int n0   = blockIdx.x * 128;
    const int K    = DIM;

    const int lr  = tid >> 2;
    const int c8  = (tid & 3) * 8;

    const int l15 = lane & 15;
    const int a_co = (lane >> 4) << 3;
    const int l7  = lane & 7;
    const int b_co = ((lane >> 3) & 1) << 3;

    float acc[4][4][4];
    #pragma unroll
    for (int i = 0; i < 4; i++)
        #pragma unroll
        for (int j = 0; j < 4; j++)
            #pragma unroll
            for (int r = 0; r < 4; r++) acc[i][j][r] = 0.f;

    const int KT = K >> 5;   // 16

    auto load_stage = [&](int st, int kt) {
        const int kc = kt * 32 + c8;
        #pragma unroll
        for (int half = 0; half < 2; half++) {
            const int r = lr + 64 * half;
            cp_async16(&As[st][r][c8], A + (size_t)(m0 + r) * K + kc, true);
            cp_async16(&Bs[st][r][c8], B + (size_t)(n0 + r) * K + kc, true);
        }
    };

    load_stage(0, 0);
    cp_commit();
    load_stage(1, 1);
    cp_commit();

    for (int kt = 0; kt < KT; kt++) {
        cp_wait1();
        __syncthreads();
        if (kt + 2 < KT) load_stage((kt + 2) % 3, kt + 2);
        cp_commit();

        const int st = kt % 3;
        #pragma unroll
        for (int ks = 0; ks < 2; ks++) {
            uint32_t afr[4][4], bfr[4][2];
            #pragma unroll
            for (int i = 0; i < 4; i++)
                ldmatrix_x4(afr[i], &As[st][wm*64 + i*16 + l15][ks*16 + a_co]);
            #pragma unroll
            for (int j = 0; j < 4; j++)
                ldmatrix_x2(bfr[j], &Bs[st][wn*32 + j*8 + l7][ks*16 + b_co]);
            #pragma unroll
            for (int i = 0; i < 4; i++)
                #pragma unroll
                for (int j = 0; j < 4; j++)
                    mma_bf16(acc[i][j], afr[i], bfr[j]);
        }
    }

    #pragma unroll
    for (int i = 0; i < 4; i++) {
        const int row = m0 + wm * 64 + i * 16 + qr;
        #pragma unroll
        for (int j = 0; j < 4; j++) {
            const int col = n0 + wn * 32 + j * 8 + 2 * qc;
            const float2 bi = *(const float2*)(bias + col);
            float v0 = acc[i][j][0] + bi.x;
            float v1 = acc[i][j][1] + bi.y;
            float v2 = acc[i][j][2] + bi.x;
            float v3 = acc[i][j][3] + bi.y;
            __nv_bfloat16* dst = (col < DIM) ? Qo : (col < 2*DIM ? Ko : Vo);
            const int lc = col & (DIM - 1);
            *(uint32_t*)(dst + (size_t)row * DIM + lc)       = pack_bf16(v0, v1);
            *(uint32_t*)(dst + (size_t)(row + 8) * DIM + lc) = pack_bf16(v2, v3);
        }
    }
}

// ---------------- BF16 flash attention (R10, unchanged) ------------------------
#define APB 72
__global__ void __launch_bounds__(256)
attn_bf16_kernel(const __nv_bfloat16* __restrict__ Q, const __nv_bfloat16* __restrict__ K,
                 const __nv_bfloat16* __restrict__ V, __nv_bfloat16* __restrict__ O)
{
    extern __shared__ __nv_bfloat16 smb[];
    __nv_bfloat16* Qs = smb;                   // [128][APB]
    __nv_bfloat16* Ks = smb + 128*APB;         // [2][64][APB]
    __nv_bfloat16* Vs = Ks + 2*64*APB;         // [2][64][APB]

    const int tid  = threadIdx.x;
    const int w    = tid >> 5;
    const int lane = tid & 31;
    const int qr   = lane >> 2;
    const int qc   = lane & 3;
    const int bh   = blockIdx.y;
    const int b    = bh >> 3, h = bh & 7;
    const int q0   = blockIdx.x * 128;
    const __nv_bfloat16* Qp = Q + ((size_t)b * SEQ + q0) * DIM + h * DK;
    const __nv_bfloat16* Kp = K + ((size_t)b * SEQ) * DIM + h * DK;
    const __nv_bfloat16* Vp = V + ((size_t)b * SEQ) * DIM + h * DK;
    const int mb = w * 16;

    const int l15 = lane & 15;
    const int a_co = (lane >> 4) << 3;
    const int l7  = lane & 7;
    const int b_co = ((lane >> 3) & 1) << 3;

    #pragma unroll
    for (int it = 0; it < 4; it++) {
        const int idx = tid + 256 * it;
        const int r = idx >> 3, cc8 = (idx & 7) * 8;
        *(uint4*)&Qs[r*APB + cc8] = *(const uint4*)(Qp + (size_t)r * DIM + cc8);
    }

    const int kvr = tid >> 2;
    const int kvc = (tid & 3) * 16;
    auto load_kv = [&](int st, int kt) {
        const int t0 = kt * 64;
        const size_t gofs = (size_t)(t0 + kvr) * DIM;
        __nv_bfloat16* kd = Ks + (st*64 + kvr)*APB;
        __nv_bfloat16* vd = Vs + (st*64 + kvr)*APB;
        cp_async16(kd + kvc,     Kp + gofs + kvc,     true);
        cp_async16(kd + kvc + 8, Kp + gofs + kvc + 8, true);
        cp_async16(vd + kvc,     Vp + gofs + kvc,     true);
        cp_async16(vd + kvc + 8, Vp + gofs + kvc + 8, true);
    };
    load_kv(0, 0); cp_commit();

    __syncthreads();
    uint32_t qf[4][4];
    #pragma unroll
    for (int ks = 0; ks < 4; ks++)
        ldmatrix_x4(qf[ks], &Qs[(mb + l15)*APB + ks*16 + a_co]);

    float o[8][4];
    #pragma unroll
    for (int j = 0; j < 8; j++)
        #pragma unroll
        for (int r = 0; r < 4; r++) o[j][r] = 0.f;
    float rowm0 = -1e30f, rowm1 = -1e30f, rowl0 = 0.f, rowl1 = 0.f;

    const int NT = SEQ / 64;
    for (int kt = 0; kt < NT; kt++) {
        if (kt + 1 < NT) load_kv((kt + 1) & 1, kt + 1);
        cp_commit();
        cp_wait1();
        __syncthreads();
        const int st = kt & 1;

        float s[8][4];
        #pragma unroll
        for (int j = 0; j < 8; j++)
            #pragma unroll
            for (int r = 0; r < 4; r++) s[j][r] = 0.f;
        #pragma unroll
        for (int ks = 0; ks < 4; ks++) {
            #pragma unroll
            for (int j = 0; j < 8; j++) {
                uint32_t bf[2];
                ldmatrix_x2(bf, &Ks[(st*64 + j*8 + l7)*APB + ks*16 + b_co]);
                mma_bf16(s[j], qf[ks], bf);
            }
        }

        float mt0 = -1e30f, mt1 = -1e30f;
        #pragma unroll
        for (int j = 0; j < 8; j++) {
            mt0 = fmaxf(mt0, fmaxf(s[j][0], s[j][1]));
            mt1 = fmaxf(mt1, fmaxf(s[j][2], s[j][3]));
        }
        mt0 = fmaxf(mt0, __shfl_xor_sync(0xffffffffu, mt0, 1));
        mt0 = fmaxf(mt0, __shfl_xor_sync(0xffffffffu, mt0, 2));
        mt1 = fmaxf(mt1, __shfl_xor_sync(0xffffffffu, mt1, 1));
        mt1 = fmaxf(mt1, __shfl_xor_sync(0xffffffffu, mt1, 2));

        const float mn0 = fmaxf(rowm0, mt0), mn1 = fmaxf(rowm1, mt1);
        const float sc0 = fexp2(rowm0 - mn0), sc1 = fexp2(rowm1 - mn1);
        rowm0 = mn0; rowm1 = mn1;

        float ps0 = 0.f, ps1 = 0.f;
        #pragma unroll
        for (int j = 0; j < 8; j++) {
            s[j][0] = fexp2(s[j][0] - mn0);
            s[j][1] = fexp2(s[j][1] - mn0);
            s[j][2] = fexp2(s[j][2] - mn1);
            s[j][3] = fexp2(s[j][3] - mn1);
            ps0 += s[j][0] + s[j][1];
            ps1 += s[j][2] + s[j][3];
        }
        ps0 += __shfl_xor_sync(0xffffffffu, ps0, 1);
        ps0 += __shfl_xor_sync(0xffffffffu, ps0, 2);
        ps1 += __shfl_xor_sync(0xffffffffu, ps1, 1);
        ps1 += __shfl_xor_sync(0xffffffffu, ps1, 2);
        rowl0 = rowl0 * sc0 + ps0;
        rowl1 = rowl1 * sc1 + ps1;

        #pragma unroll
        for (int j = 0; j < 8; j++) {
            o[j][0] *= sc0; o[j][1] *= sc0;
            o[j][2] *= sc1; o[j][3] *= sc1;
        }

        #pragma unroll
        for (int kb = 0; kb < 4; kb++) {
            uint32_t a[4];
            a[0] = pack_bf16(s[2*kb  ][0], s[2*kb  ][1]);
            a[1] = pack_bf16(s[2*kb  ][2], s[2*kb  ][3]);
            a[2] = pack_bf16(s[2*kb+1][0], s[2*kb+1][1]);
            a[3] = pack_bf16(s[2*kb+1][2], s[2*kb+1][3]);
            #pragma unroll
            for (int j = 0; j < 8; j++) {
                uint32_t bf[2];
                ldmatrix_x2t(bf, &Vs[(st*64 + kb*16 + l15)*APB + j*8]);
                mma_bf16(o[j], a, bf);
            }
        }
        __syncthreads();
    }

    const float inv0 = 1.f / rowl0, inv1 = 1.f / rowl1;
    const int r0 = q0 + mb + qr, r1 = r0 + 8;
    #pragma unroll
    for (int j = 0; j < 8; j++) {
        const int col = h * DK + j * 8 + 2 * qc;
        *(uint32_t*)(O + ((size_t)b * SEQ + r0) * DIM + col) =
            pack_bf16(o[j][0] * inv0, o[j][1] * inv0);
        *(uint32_t*)(O + ((size_t)b * SEQ + r1) * DIM + col) =
            pack_bf16(o[j][2] * inv1, o[j][3] * inv1);
    }
}

// ---------------- LayerNorm helpers (R10, unchanged) ---------------------------
__global__ void ln_final_kernel(const float* __restrict__ psum, const float* __restrict__ psq,
                                float* __restrict__ mean, float* __restrict__ rstd)
{
    const int b = blockIdx.x;
    float s = psum[b*64 + threadIdx.x];
    float q = psq [b*64 + threadIdx.x];
    #pragma unroll
    for (int off = 16; off; off >>= 1) {
        s += __shfl_down_sync(0xffffffffu, s, off);
        q += __shfl_down_sync(0xffffffffu, q, off);
    }
    __shared__ float ws[2], wq[2];
    if ((threadIdx.x & 31) == 0) { ws[threadIdx.x >> 5] = s; wq[threadIdx.x >> 5] = q; }
    __syncthreads();
    if (threadIdx.x == 0) {
        float S = ws[0] + ws[1], Q = wq[0] + wq[1];
        float m = S / (float)SD;
        float v = Q / (float)SD - m * m;
        mean[b] = m;
        rstd[b] = rsqrtf(v + LN_EPS);
    }
}

__global__ void ln_final16_kernel(const float* __restrict__ psum, const float* __restrict__ psq,
                                  float* __restrict__ mean, float* __restrict__ rstd)
{
    const int b = blockIdx.x;
    const int l = threadIdx.x;
    float s = (l < 16) ? psum[b*16 + l] : 0.f;
    float q = (l < 16) ? psq [b*16 + l] : 0.f;
    #pragma unroll
    for (int off = 8; off; off >>= 1) {
        s += __shfl_down_sync(0xffffffffu, s, off);
        q += __shfl_down_sync(0xffffffffu, q, off);
    }
    if (l == 0) {
        float m = s / (float)SD;
        float v = q / (float)SD - m * m;
        mean[b] = m;
        rstd[b] = rsqrtf(v + LN_EPS);
    }
}

__global__ void ln_apply_bf16_kernel(const float* __restrict__ X,
                                     const float* __restrict__ gamma, const float* __restrict__ beta,
                                     const float* __restrict__ mean, const float* __restrict__ rstd,
                                     __nv_bfloat16* __restrict__ Yb)
{
    const float4* x4 = (const float4*)X;
    const float4* g4 = (const float4*)gamma;
    const float4* b4 = (const float4*)beta;
    const int total = BATCH * (SD/4);
    for (int idx = blockIdx.x * blockDim.x + threadIdx.x; idx < total;
         idx += gridDim.x * blockDim.x) {
        const int b   = idx >> 16;
        const int loc = idx & 65535;
        const float m = mean[b], r = rstd[b];
        float4 v = x4[idx], g = g4[loc], be = b4[loc];
        uint2 p;
        p.x = pack_bf16((v.x - m) * r * g.x + be.x, (v.y - m) * r * g.y + be.y);
        p.y = pack_bf16((v.z - m) * r * g.z + be.z, (v.w - m) * r * g.w + be.w);
        ((uint2*)Yb)[idx] = p;
    }
}

__global__ void ln_stats_y2_kernel(const float* __restrict__ Z,
                                   const float* __restrict__ gamma, const float* __restrict__ beta,
                                   const float* __restrict__ mean2, const float* __restrict__ rstd2,
                                   float* __restrict__ psum, float* __restrict__ psq)
{
    const int b = blockIdx.y, chunk = blockIdx.x;
    const size_t base = (size_t)b * SD + (size_t)chunk * 4096;
    const float4* z4 = (const float4*)(Z + base);
    const float4* g4 = (const float4*)(gamma + (size_t)chunk * 4096);
    const float4* b4 = (const float4*)(beta  + (size_t)chunk * 4096);
    const float m = mean2[b], r = rstd2[b];
    float s = 0.f, q = 0.f;
    #pragma unroll
    for (int i = 0; i < 4; i++) {
        const int t = threadIdx.x + 256*i;
        float4 v = z4[t], g = g4[t], be = b4[t];
        float4 y;
        y.x = (v.x - m) * r * g.x + be.x;
        y.y = (v.y - m) * r * g.y + be.y;
        y.z = (v.z - m) * r * g.z + be.z;
        y.w = (v.w - m) * r * g.w + be.w;
        s += y.x + y.y + y.z + y.w;
        q += y.x*y.x + y.y*y.y + y.z*y.z + y.w*y.w;
    }
    #pragma unroll
    for (int off = 16; off; off >>= 1) {
        s += __shfl_down_sync(0xffffffffu, s, off);
        q += __shfl_down_sync(0xffffffffu, q, off);
    }
    __shared__ float ws[8], wq[8];
    if ((threadIdx.x & 31) == 0) { ws[threadIdx.x >> 5] = s; wq[threadIdx.x >> 5] = q; }
    __syncthreads();
    if (threadIdx.x == 0) {
        float S = 0.f, Q = 0.f;
        #pragma unroll
        for (int w = 0; w < 8; w++) { S += ws[w]; Q += wq[w]; }
        psum[b*64 + chunk] = S;
        psq [b*64 + chunk] = Q;
    }
}

__global__ void ln_apply_y2_kernel(const float* __restrict__ Z,
                                   const float* __restrict__ gamma, const float* __restrict__ beta,
                                   const float* __restrict__ mean2, const float* __restrict__ rstd2,
                                   const float* __restrict__ mean3, const float* __restrict__ rstd3,
                                   float* __restrict__ out)
{
    const float4* z4 = (const float4*)Z;
    const float4* g4 = (const float4*)gamma;
    const float4* b4 = (const float4*)beta;
    float4* o4 = (float4*)out;
    const int total = BATCH * (SD/4);
    for (int idx = blockIdx.x * blockDim.x + threadIdx.x; idx < total;
         idx += gridDim.x * blockDim.x) {
        const int b   = idx >> 16;
        const int loc = idx & 65535;
        const float m2 = mean2[b], r2 = rstd2[b];
        const float m3 = mean3[b], r3 = rstd3[b];
        float4 v = z4[idx], g = g4[loc], be = b4[loc];
        float4 y, o;
        y.x = (v.x - m2) * r2 * g.x + be.x;
        y.y = (v.y - m2) * r2 * g.y + be.y;
        y.z = (v.z - m2) * r2 * g.z + be.z;
        y.w = (v.w - m2) * r2 * g.w + be.w;
        o.x = (y.x - m3) * r3 * g.x + be.x;
        o.y = (y.y - m3) * r3 * g.y + be.y;
        o.z = (y.z - m3) * r3 * g.z + be.z;
        o.w = (y.w - m3) * r3 * g.w + be.w;
        o4[idx] = o;
    }
}

// ---------------- launch ------------------------------------------------------
#define ATTN_SMEM ((128*APB + 4*64*APB) * 2)   // 55296 bytes

extern "C" void kernel_launch(void* const* d_in, const int* in_sizes, int n_in,
                              void* d_out, int out_size)
{
    const float* x     = (const float*)d_in[0];
    const float* Wq    = (const float*)d_in[1];
    const float* bq    = (const float*)d_in[2];
    const float* Wk    = (const float*)d_in[3];
    const float* bk    = (const float*)d_in[4];
    const float* Wv    = (const float*)d_in[5];
    const float* bv    = (const float*)d_in[6];
    const float* Wo    = (const float*)d_in[7];
    const float* bo    = (const float*)d_in[8];
    const float* W1    = (const float*)d_in[9];
    const float* b1    = (const float*)d_in[10];
    const float* W2    = (const float*)d_in[11];
    const float* b2    = (const float*)d_in[12];
    const float* W3    = (const float*)d_in[13];
    const float* b3    = (const float*)d_in[14];
    const float* gamma = (const float*)d_in[15];
    const float* beta  = (const float*)d_in[16];
    float* out = (float*)d_out;

    float *y0_, *z_, *psum_, *psq_, *mean_, *rstd_, *bqkv_;
    cudaGetSymbolAddress((void**)&y0_, g_y0);
    cudaGetSymbolAddress((void**)&z_,  g_z);
    cudaGetSymbolAddress((void**)&psum_, g_psum);
    cudaGetSymbolAddress((void**)&psq_,  g_psq);
    cudaGetSymbolAddress((void**)&mean_, g_mean);
    cudaGetSymbolAddress((void**)&rstd_, g_rstd);
    cudaGetSymbolAddress((void**)&bqkv_, g_bqkv);

    __nv_bfloat16 *xb, *qb, *kb, *vb, *ccb, *y1b, *f1b, *f2b;
    __nv_bfloat16 *wqkvb, *wob, *w1b, *w2b, *w3b;
    cudaGetSymbolAddress((void**)&xb,    gb_x);
    cudaGetSymbolAddress((void**)&qb,    gb_q);
    cudaGetSymbolAddress((void**)&kb,    gb_k);
    cudaGetSymbolAddress((void**)&vb,    gb_v);
    cudaGetSymbolAddress((void**)&ccb,   gb_cc);
    cudaGetSymbolAddress((void**)&y1b,   gb_y1);
    cudaGetSymbolAddress((void**)&f1b,   gb_f1);
    cudaGetSymbolAddress((void**)&f2b,   gb_f2);
    cudaGetSymbolAddress((void**)&wqkvb, gb_wqkv);
    cudaGetSymbolAddress((void**)&wob,   gb_wo);
    cudaGetSymbolAddress((void**)&w1b,   gb_w1);
    cudaGetSymbolAddress((void**)&w2b,   gb_w2);
    cudaGetSymbolAddress((void**)&w3b,   gb_w3);

    float* mean1_ = mean_;            float* rstd1_ = rstd_;
    float* mean2_ = mean_ + BATCH;    float* rstd2_ = rstd_ + BATCH;
    float* mean3_ = mean_ + 2*BATCH;  float* rstd3_ = rstd_ + 2*BATCH;

    cudaFuncSetAttribute(attn_bf16_kernel,
                         cudaFuncAttributeMaxDynamicSharedMemorySize, ATTN_SMEM);

    // all converts in ONE launch; Wq pre-scaled by (1/8)*log2(e)
    CvtArgs ca;
    ca.seg[0] = { x,  xb,                  (MTOT*DIM)/4, 1.f    };
    ca.seg[1] = { Wq, wqkvb,               (DIM*DIM)/4,  QSCALE };
    ca.seg[2] = { Wk, wqkvb + DIM*DIM,     (DIM*DIM)/4,  1.f    };
    ca.seg[3] = { Wv, wqkvb + 2*DIM*DIM,   (DIM*DIM)/4,  1.f    };
    ca.seg[4] = { Wo, wob,                 (DIM*DIM)/4,  1.f    };
    ca.seg[5] = { W1, w1b,                 (FF*DIM)/4,   1.f    };
    ca.seg[6] = { W2, w2b,                 (FF*FF)/4,    1.f    };
    ca.seg[7] = { W3, w3b,                 (DIM*FF)/4,   1.f    };
    cvt_multi<<<1024, 256>>>(ca);
    build_bias_qkv<<<(QKN + 255)/256, 256>>>(bq, bk, bv, bqkv_);

    // fused QKV projection
    gemm_qkv_kernel<<<dim3(12, 128), 256>>>(xb, wqkvb, bqkv_, qb, kb, vb);

    // attention (128 q-rows per block)
    attn_bf16_kernel<<<dim3(SEQ/128, BATCH*HEADS), 256, ATTN_SMEM>>>(qb, kb, vb, ccb);

    // output projection + bias + residual(x) -> fp32 y0, fused LN1 partial stats
    gemm_bf16_kernel<<<dim3(4, 128), 256>>>(ccb, wob, bo, x, y0_, nullptr,
                                            MTOT, DIM, DIM, 0, psum_, psq_,
                                            nullptr, nullptr, nullptr, nullptr, nullptr);

    // LN1 -> y1b (bf16 only)
    ln_final16_kernel<<<BATCH, 32>>>(psum_, psq_, mean1_, rstd1_);
    ln_apply_bf16_kernel<<<2048, 256>>>(y0_, gamma, beta, mean1_, rstd1_, y1b);

    // FFN
    gemm_bf16_kernel<<<dim3(2, 128), 256>>>(y1b, w1b, b1, nullptr, nullptr, f1b,
                                            MTOT, FF, DIM, 1, nullptr, nullptr,
                                            nullptr, nullptr, nullptr, nullptr, nullptr);
    gemm_bf16_kernel<<<dim3(2, 128), 256>>>(f1b, w2b, b2, nullptr, nullptr, f2b,
                                            MTOT, FF, FF, 1, nullptr, nullptr,
                                            nullptr, nullptr, nullptr, nullptr, nullptr);
    // W3: residual y1 recomputed on the fly from y0 + LN1 params; fused LN2 stats
    gemm_bf16_kernel<<<dim3(4, 128), 256>>>(f2b, w3b, b3, nullptr, z_, nullptr,
                                            MTOT, DIM, FF, 0, psum_, psq_,
                                            y0_, gamma, beta, mean1_, rstd1_);

    // LN2 stats -> m2/r2; y2 stats on the fly -> m3/r3; fused double-apply -> out
    ln_final16_kernel<<<BATCH, 32>>>(psum_, psq_, mean2_, rstd2_);
    ln_stats_y2_kernel<<<dim3(64, BATCH), 256>>>(z_, gamma, beta, mean2_, rstd2_, psum_, psq_);
    ln_final_kernel<<<BATCH, 64>>>(psum_, psq_, mean3_, rstd3_);
    ln_apply_y2_kernel<<<2048, 256>>>(z_, gamma, beta, mean2_, rstd2_, mean3_, rstd3_, out);
}

// round 15
// speedup vs baseline: 1.0643x; 1.0059x over previous
#include <cuda_runtime.h>
#include <cuda_bf16.h>
#include <cstdint>
#include <cstdio>

// Problem constants
#define BATCH 32
#define SEQ   512
#define DIM   512
#define HEADS 8
#define DK    64
#define FF    200
#define MTOT  (BATCH*SEQ)        // 16384
#define SD    (SEQ*DIM)          // 262144
#define QKN   (3*DIM)            // 1536 fused QKV width
#define LN_EPS 1e-5f
#define QSCALE (0.125f * 1.44269504088896340736f)   // 1/8 * log2(e)

// ---------------- scratch (device globals; no allocation allowed) -------------
__device__ float g_y0[MTOT*DIM];
__device__ float g_z [MTOT*DIM];
__device__ float g_psum[BATCH*64];
__device__ float g_psq [BATCH*64];
__device__ float g_mean[3*BATCH];
__device__ float g_rstd[3*BATCH];
__device__ float g_bqkv[QKN];
__device__ int   g_ctr[4];

__device__ __nv_bfloat16 gb_x [MTOT*DIM];
__device__ __nv_bfloat16 gb_q [MTOT*DIM];
__device__ __nv_bfloat16 gb_k [MTOT*DIM];
__device__ __nv_bfloat16 gb_v [MTOT*DIM];
__device__ __nv_bfloat16 gb_cc[MTOT*DIM];
__device__ __nv_bfloat16 gb_y1[MTOT*DIM];
__device__ __nv_bfloat16 gb_f1[MTOT*FF];
__device__ __nv_bfloat16 gb_f2[MTOT*FF];
__device__ __nv_bfloat16 gb_wqkv[QKN*DIM];
__device__ __nv_bfloat16 gb_wo[DIM*DIM];
__device__ __nv_bfloat16 gb_w1[FF*DIM];
__device__ __nv_bfloat16 gb_w2[FF*FF];
__device__ __nv_bfloat16 gb_w3[DIM*FF];

// ---------------- helpers ------------------------------------------------------
__device__ __forceinline__ uint32_t pack_bf16(float a, float b) {
    __nv_bfloat162 h = __floats2bfloat162_rn(a, b);
    return *(uint32_t*)&h;
}

__device__ __forceinline__ float fexp2(float x) {
    float y;
    asm("ex2.approx.ftz.f32 %0, %1;" : "=f"(y) : "f"(x));
    return y;
}

__device__ __forceinline__ void mma_bf16(float* c, const uint32_t* a, const uint32_t* b) {
    asm volatile(
        "mma.sync.aligned.m16n8k16.row.col.f32.bf16.bf16.f32 "
        "{%0,%1,%2,%3}, {%4,%5,%6,%7}, {%8,%9}, {%0,%1,%2,%3};\n"
        : "+f"(c[0]), "+f"(c[1]), "+f"(c[2]), "+f"(c[3])
        : "r"(a[0]), "r"(a[1]), "r"(a[2]), "r"(a[3]),
          "r"(b[0]), "r"(b[1]));
}

__device__ __forceinline__ void ldmatrix_x4(uint32_t* r, const void* p) {
    uint32_t a = (uint32_t)__cvta_generic_to_shared(p);
    asm volatile("ldmatrix.sync.aligned.m8n8.x4.shared.b16 {%0,%1,%2,%3}, [%4];"
                 : "=r"(r[0]), "=r"(r[1]), "=r"(r[2]), "=r"(r[3]) : "r"(a));
}
__device__ __forceinline__ void ldmatrix_x2(uint32_t* r, const void* p) {
    uint32_t a = (uint32_t)__cvta_generic_to_shared(p);
    asm volatile("ldmatrix.sync.aligned.m8n8.x2.shared.b16 {%0,%1}, [%2];"
                 : "=r"(r[0]), "=r"(r[1]) : "r"(a));
}
__device__ __forceinline__ void ldmatrix_x2t(uint32_t* r, const void* p) {
    uint32_t a = (uint32_t)__cvta_generic_to_shared(p);
    asm volatile("ldmatrix.sync.aligned.m8n8.x2.trans.shared.b16 {%0,%1}, [%2];"
                 : "=r"(r[0]), "=r"(r[1]) : "r"(a));
}

__device__ __forceinline__ void cp_async16(void* smem, const void* gmem, bool valid) {
    uint32_t s = (uint32_t)__cvta_generic_to_shared(smem);
    int sz = valid ? 16 : 0;
    asm volatile("cp.async.cg.shared.global [%0], [%1], 16, %2;"
                 :: "r"(s), "l"(gmem), "r"(sz));
}
__device__ __forceinline__ void cp_commit() { asm volatile("cp.async.commit_group;"); }
__device__ __forceinline__ void cp_wait1()  { asm volatile("cp.async.wait_group 1;"); }

// ---------------- converts + bias + counter reset (single launch) --------------
struct CvtSeg  { const float* src; __nv_bfloat16* dst; int n4; float scale; };
struct CvtArgs { CvtSeg seg[8]; };

__global__ void cvt_multi(CvtArgs a, const float* __restrict__ bq,
                          const float* __restrict__ bk, const float* __restrict__ bv,
                          float* __restrict__ bqkv, int* __restrict__ ctr)
{
    const int gi = blockIdx.x * blockDim.x + threadIdx.x;
    if (gi < 4) ctr[gi] = 0;
    if (gi < QKN) {
        float v;
        if (gi < DIM)        v = bq[gi] * QSCALE;
        else if (gi < 2*DIM) v = bk[gi - DIM];
        else                 v = bv[gi - 2*DIM];
        bqkv[gi] = v;
    }
    #pragma unroll
    for (int sg = 0; sg < 8; sg++) {
        const float* src = a.seg[sg].src;
        __nv_bfloat16* dst = a.seg[sg].dst;
        const int n4 = a.seg[sg].n4;
        const float sc = a.seg[sg].scale;
        for (int i = gi; i < n4; i += gridDim.x * blockDim.x) {
            float4 v = ((const float4*)src)[i];
            uint2 p;
            p.x = pack_bf16(v.x * sc, v.y * sc);
            p.y = pack_bf16(v.z * sc, v.w * sc);
            ((uint2*)dst)[i] = p;
        }
    }
}

// ---------------- BF16 GEMM: 128x128, BK=32, 2-stage cp.async ------------------
// optional fused LN partial stats + last-block final reduction (fctr/fmean/frstd);
// optional on-the-fly LN residual (lnx + lnmean/lnrstd inputs)
#define GP 40
__global__ void __launch_bounds__(256)
gemm_bf16_kernel(const __nv_bfloat16* __restrict__ A, const __nv_bfloat16* __restrict__ B,
                 const float* __restrict__ bias, const float* __restrict__ res,
                 float* __restrict__ C, __nv_bfloat16* __restrict__ Cb,
                 int M, int N, int K, int relu,
                 float* __restrict__ psum, float* __restrict__ psq,
                 const float* __restrict__ lnx, const float* __restrict__ lngam,
                 const float* __restrict__ lnbet, const float* __restrict__ lnmean,
                 const float* __restrict__ lnrstd,
                 int* __restrict__ fctr, float* __restrict__ fmean,
                 float* __restrict__ frstd)
{
    __shared__ __nv_bfloat16 As[2][128][GP];
    __shared__ __nv_bfloat16 Bs[2][128][GP];
    __shared__ float sred[8], qred[8];
    __shared__ int s_last;

    const int tid  = threadIdx.x;
    const int wid  = tid >> 5;
    const int lane = tid & 31;
    const int wm   = wid >> 2;
    const int wn   = wid & 3;
    const int qr   = lane >> 2;
    const int qc   = lane & 3;
    const int m0   = blockIdx.y * 128;
    const int n0   = blockIdx.x * 128;

    const int lr  = tid >> 2;
    const int c8  = (tid & 3) * 8;

    const int l15 = lane & 15;
    const int a_co = (lane >> 4) << 3;
    const int l7  = lane & 7;
    const int b_co = ((lane >> 3) & 1) << 3;

    float acc[4][4][4];
    #pragma unroll
    for (int i = 0; i < 4; i++)
        #pragma unroll
        for (int j = 0; j < 4; j++)
            #pragma unroll
            for (int r = 0; r < 4; r++) acc[i][j][r] = 0.f;

    const int KT = (K + 31) >> 5;

    auto load_stage = [&](int st, int kt) {
        const int kc = kt * 32 + c8;
        const bool kok = (kc < K);
        #pragma unroll
        for (int half = 0; half < 2; half++) {
            const int r = lr + 64 * half;
            cp_async16(&As[st][r][c8], A + (size_t)(m0 + r) * K + kc, kok);
            const int n = n0 + r;
            cp_async16(&Bs[st][r][c8], B + (size_t)n * K + kc, kok && (n < N));
        }
    };

    load_stage(0, 0);
    cp_commit();

    for (int kt = 0; kt < KT; kt++) {
        if (kt + 1 < KT) load_stage((kt + 1) & 1, kt + 1);
        cp_commit();
        cp_wait1();
        __syncthreads();

        const int st = kt & 1;
        #pragma unroll
        for (int ks = 0; ks < 2; ks++) {
            uint32_t afr[4][4], bfr[4][2];
            #pragma unroll
            for (int i = 0; i < 4; i++)
                ldmatrix_x4(afr[i], &As[st][wm*64 + i*16 + l15][ks*16 + a_co]);
            #pragma unroll
            for (int j = 0; j < 4; j++)
                ldmatrix_x2(bfr[j], &Bs[st][wn*32 + j*8 + l7][ks*16 + b_co]);
            #pragma unroll
            for (int i = 0; i < 4; i++)
                #pragma unroll
                for (int j = 0; j < 4; j++)
                    mma_bf16(acc[i][j], afr[i], bfr[j]);
        }
        __syncthreads();
    }

    float ts = 0.f, tq = 0.f;
    #pragma unroll
    for (int i = 0; i < 4; i++) {
        const int row = m0 + wm * 64 + i * 16 + qr;
        #pragma unroll
        for (int j = 0; j < 4; j++) {
            const int col = n0 + wn * 32 + j * 8 + 2 * qc;
            if (col < N) {
                const float2 bi = *(const float2*)(bias + col);
                float v0 = acc[i][j][0] + bi.x;
                float v1 = acc[i][j][1] + bi.y;
                float v2 = acc[i][j][2] + bi.x;
                float v3 = acc[i][j][3] + bi.y;
                if (res) {
                    const float2 r0 = *(const float2*)(res + (size_t)row * N + col);
                    const float2 r1 = *(const float2*)(res + (size_t)(row + 8) * N + col);
                    v0 += r0.x; v1 += r0.y; v2 += r1.x; v3 += r1.y;
                }
                if (lnx) {
                    const int bidx = row >> 9;
                    const float m1 = lnmean[bidx], r1s = lnrstd[bidx];
                    const int sr0 = row & 511, sr1 = (row + 8) & 511;
                    const float2 x0 = *(const float2*)(lnx + (size_t)row * N + col);
                    const float2 x1 = *(const float2*)(lnx + (size_t)(row + 8) * N + col);
                    const float2 g0 = *(const float2*)(lngam + (size_t)sr0 * N + col);
                    const float2 e0 = *(const float2*)(lnbet + (size_t)sr0 * N + col);
                    const float2 g1 = *(const float2*)(lngam + (size_t)sr1 * N + col);
                    const float2 e1 = *(const float2*)(lnbet + (size_t)sr1 * N + col);
                    v0 += (x0.x - m1) * r1s * g0.x + e0.x;
                    v1 += (x0.y - m1) * r1s * g0.y + e0.y;
                    v2 += (x1.x - m1) * r1s * g1.x + e1.x;
                    v3 += (x1.y - m1) * r1s * g1.y + e1.y;
                }
                if (relu) {
                    v0 = fmaxf(v0, 0.f); v1 = fmaxf(v1, 0.f);
                    v2 = fmaxf(v2, 0.f); v3 = fmaxf(v3, 0.f);
                }
                if (C) {
                    *(float2*)(C + (size_t)row * N + col)       = make_float2(v0, v1);
                    *(float2*)(C + (size_t)(row + 8) * N + col) = make_float2(v2, v3);
                }
                if (Cb) {
                    *(uint32_t*)(Cb + (size_t)row * N + col)       = pack_bf16(v0, v1);
                    *(uint32_t*)(Cb + (size_t)(row + 8) * N + col) = pack_bf16(v2, v3);
                }
                if (psum) {
                    ts += v0 + v1 + v2 + v3;
                    tq += v0*v0 + v1*v1 + v2*v2 + v3*v3;
                }
            }
        }
    }

    if (psum) {
        #pragma unroll
        for (int off = 16; off; off >>= 1) {
            ts += __shfl_xor_sync(0xffffffffu, ts, off);
            tq += __shfl_xor_sync(0xffffffffu, tq, off);
        }
        if (lane == 0) { sred[wid] = ts; qred[wid] = tq; }
        __syncthreads();
        if (tid == 0) {
            float S = 0.f, Q = 0.f;
            #pragma unroll
            for (int w = 0; w < 8; w++) { S += sred[w]; Q += qred[w]; }
            const int slot = (blockIdx.y >> 2) * 16 + (blockIdx.y & 3) * 4 + blockIdx.x;
            psum[slot] = S;
            psq [slot] = Q;
            __threadfence();
            const int prev = atomicAdd(fctr, 1);
            s_last = (prev == (int)(gridDim.x * gridDim.y) - 1);
        }
        __syncthreads();
        // last finishing block reduces all batches' 16 partials -> mean/rstd
        if (s_last && tid < BATCH) {
            float S = 0.f, Q = 0.f;
            #pragma unroll
            for (int t = 0; t < 16; t++) { S += psum[tid*16 + t]; Q += psq[tid*16 + t]; }
            const float m = S / (float)SD;
            fmean[tid] = m;
            frstd[tid] = rsqrtf(Q / (float)SD - m * m + LN_EPS);
        }
    }
}

// QKV GEMM: A[M,512] x Wqkv[1536,512]^T; epilogue splits cols into q/k/v buffers
__global__ void __launch_bounds__(256)
gemm_qkv_kernel(const __nv_bfloat16* __restrict__ A, const __nv_bfloat16* __restrict__ B,
                const float* __restrict__ bias,
                __nv_bfloat16* __restrict__ Qo, __nv_bfloat16* __restrict__ Ko,
                __nv_bfloat16* __restrict__ Vo)
{
    __shared__ __nv_bfloat16 As[2][128][GP];
    __shared__ __nv_bfloat16 Bs[2][128][GP];

    const int tid  = threadIdx.x;
    const int wid  = tid >> 5;
    const int lane = tid & 31;
    const int wm   = wid >> 2;
    const int wn   = wid & 3;
    const int qr   = lane >> 2;
    const int qc   = lane & 3;
    const int m0   = blockIdx.y * 128;
    const int n0   = blockIdx.x * 128;
    const int K    = DIM;

    const int lr  = tid >> 2;
    const int c8  = (tid & 3) * 8;

    const int l15 = lane & 15;
    const int a_co = (lane >> 4) << 3;
    const int l7  = lane & 7;
    const int b_co = ((lane >> 3) & 1) << 3;

    float acc[4][4][4];
    #pragma unroll
    for (int i = 0; i < 4; i++)
        #pragma unroll
        for (int j = 0; j < 4; j++)
            #pragma unroll
            for (int r = 0; r < 4; r++) acc[i][j][r] = 0.f;

    const int KT = K >> 5;

    auto load_stage = [&](int st, int kt) {
        const int kc = kt * 32 + c8;
        #pragma unroll
        for (int half = 0; half < 2; half++) {
            const int r = lr + 64 * half;
            cp_async16(&As[st][r][c8], A + (size_t)(m0 + r) * K + kc, true);
            cp_async16(&Bs[st][r][c8], B + (size_t)(n0 + r) * K + kc, true);
        }
    };

    load_stage(0, 0);
    cp_commit();

    for (int kt = 0; kt < KT; kt++) {
        if (kt + 1 < KT) load_stage((kt + 1) & 1, kt + 1);
        cp_commit();
        cp_wait1();
        __syncthreads();

        const int st = kt & 1;
        #pragma unroll
        for (int ks = 0; ks < 2; ks++) {
            uint32_t afr[4][4], bfr[4][2];
            #pragma unroll
            for (int i = 0; i < 4; i++)
                ldmatrix_x4(afr[i], &As[st][wm*64 + i*16 + l15][ks*16 + a_co]);
            #pragma unroll
            for (int j = 0; j < 4; j++)
                ldmatrix_x2(bfr[j], &Bs[st][wn*32 + j*8 + l7][ks*16 + b_co]);
            #pragma unroll
            for (int i = 0; i < 4; i++)
                #pragma unroll
                for (int j = 0; j < 4; j++)
                    mma_bf16(acc[i][j], afr[i], bfr[j]);
        }
        __syncthreads();
    }

    #pragma unroll
    for (int i = 0; i < 4; i++) {
        const int row = m0 + wm * 64 + i * 16 + qr;
        #pragma unroll
        for (int j = 0; j < 4; j++) {
            const int col = n0 + wn * 32 + j * 8 + 2 * qc;
            const float2 bi = *(const float2*)(bias + col);
            float v0 = acc[i][j][0] + bi.x;
            float v1 = acc[i][j][1] + bi.y;
            float v2 = acc[i][j][2] + bi.x;
            float v3 = acc[i][j][3] + bi.y;
            __nv_bfloat16* dst = (col < DIM) ? Qo : (col < 2*DIM ? Ko : Vo);
            const int lc = col & (DIM - 1);
            *(uint32_t*)(dst + (size_t)row * DIM + lc)       = pack_bf16(v0, v1);
            *(uint32_t*)(dst + (size_t)(row + 8) * DIM + lc) = pack_bf16(v2, v3);
        }
    }
}

// ---------------- BF16 flash attention (R10, unchanged) ------------------------
#define APB 72
__global__ void __launch_bounds__(256)
attn_bf16_kernel(const __nv_bfloat16* __restrict__ Q, const __nv_bfloat16* __restrict__ K,
                 const __nv_bfloat16* __restrict__ V, __nv_bfloat16* __restrict__ O)
{
    extern __shared__ __nv_bfloat16 smb[];
    __nv_bfloat16* Qs = smb;                   // [128][APB]
    __nv_bfloat16* Ks = smb + 128*APB;         // [2][64][APB]
    __nv_bfloat16* Vs = Ks + 2*64*APB;         // [2][64][APB]

    const int tid  = threadIdx.x;
    const int w    = tid >> 5;
    const int lane = tid & 31;
    const int qr   = lane >> 2;
    const int qc   = lane & 3;
    const int bh   = blockIdx.y;
    const int b    = bh >> 3, h = bh & 7;
    const int q0   = blockIdx.x * 128;
    const __nv_bfloat16* Qp = Q + ((size_t)b * SEQ + q0) * DIM + h * DK;
    const __nv_bfloat16* Kp = K + ((size_t)b * SEQ) * DIM + h * DK;
    const __nv_bfloat16* Vp = V + ((size_t)b * SEQ) * DIM + h * DK;
    const int mb = w * 16;

    const int l15 = lane & 15;
    const int a_co = (lane >> 4) << 3;
    const int l7  = lane & 7;
    const int b_co = ((lane >> 3) & 1) << 3;

    #pragma unroll
    for (int it = 0; it < 4; it++) {
        const int idx = tid + 256 * it;
        const int r = idx >> 3, cc8 = (idx & 7) * 8;
        *(uint4*)&Qs[r*APB + cc8] = *(const uint4*)(Qp + (size_t)r * DIM + cc8);
    }

    const int kvr = tid >> 2;
    const int kvc = (tid & 3) * 16;
    auto load_kv = [&](int st, int kt) {
        const int t0 = kt * 64;
        const size_t gofs = (size_t)(t0 + kvr) * DIM;
        __nv_bfloat16* kd = Ks + (st*64 + kvr)*APB;
        __nv_bfloat16* vd = Vs + (st*64 + kvr)*APB;
        cp_async16(kd + kvc,     Kp + gofs + kvc,     true);
        cp_async16(kd + kvc + 8, Kp + gofs + kvc + 8, true);
        cp_async16(vd + kvc,     Vp + gofs + kvc,     true);
        cp_async16(vd + kvc + 8, Vp + gofs + kvc + 8, true);
    };
    load_kv(0, 0); cp_commit();

    __syncthreads();
    uint32_t qf[4][4];
    #pragma unroll
    for (int ks = 0; ks < 4; ks++)
        ldmatrix_x4(qf[ks], &Qs[(mb + l15)*APB + ks*16 + a_co]);

    float o[8][4];
    #pragma unroll
    for (int j = 0; j < 8; j++)
        #pragma unroll
        for (int r = 0; r < 4; r++) o[j][r] = 0.f;
    float rowm0 = -1e30f, rowm1 = -1e30f, rowl0 = 0.f, rowl1 = 0.f;

    const int NT = SEQ / 64;
    for (int kt = 0; kt < NT; kt++) {
        if (kt + 1 < NT) load_kv((kt + 1) & 1, kt + 1);
        cp_commit();
        cp_wait1();
        __syncthreads();
        const int st = kt & 1;

        float s[8][4];
        #pragma unroll
        for (int j = 0; j < 8; j++)
            #pragma unroll
            for (int r = 0; r < 4; r++) s[j][r] = 0.f;
        #pragma unroll
        for (int ks = 0; ks < 4; ks++) {
            #pragma unroll
            for (int j = 0; j < 8; j++) {
                uint32_t bf[2];
                ldmatrix_x2(bf, &Ks[(st*64 + j*8 + l7)*APB + ks*16 + b_co]);
                mma_bf16(s[j], qf[ks], bf);
            }
        }

        float mt0 = -1e30f, mt1 = -1e30f;
        #pragma unroll
        for (int j = 0; j < 8; j++) {
            mt0 = fmaxf(mt0, fmaxf(s[j][0], s[j][1]));
            mt1 = fmaxf(mt1, fmaxf(s[j][2], s[j][3]));
        }
        mt0 = fmaxf(mt0, __shfl_xor_sync(0xffffffffu, mt0, 1));
        mt0 = fmaxf(mt0, __shfl_xor_sync(0xffffffffu, mt0, 2));
        mt1 = fmaxf(mt1, __shfl_xor_sync(0xffffffffu, mt1, 1));
        mt1 = fmaxf(mt1, __shfl_xor_sync(0xffffffffu, mt1, 2));

        const float mn0 = fmaxf(rowm0, mt0), mn1 = fmaxf(rowm1, mt1);
        const float sc0 = fexp2(rowm0 - mn0), sc1 = fexp2(rowm1 - mn1);
        rowm0 = mn0; rowm1 = mn1;

        float ps0 = 0.f, ps1 = 0.f;
        #pragma unroll
        for (int j = 0; j < 8; j++) {
            s[j][0] = fexp2(s[j][0] - mn0);
            s[j][1] = fexp2(s[j][1] - mn0);
            s[j][2] = fexp2(s[j][2] - mn1);
            s[j][3] = fexp2(s[j][3] - mn1);
            ps0 += s[j][0] + s[j][1];
            ps1 += s[j][2] + s[j][3];
        }
        ps0 += __shfl_xor_sync(0xffffffffu, ps0, 1);
        ps0 += __shfl_xor_sync(0xffffffffu, ps0, 2);
        ps1 += __shfl_xor_sync(0xffffffffu, ps1, 1);
        ps1 += __shfl_xor_sync(0xffffffffu, ps1, 2);
        rowl0 = rowl0 * sc0 + ps0;
        rowl1 = rowl1 * sc1 + ps1;

        #pragma unroll
        for (int j = 0; j < 8; j++) {
            o[j][0] *= sc0; o[j][1] *= sc0;
            o[j][2] *= sc1; o[j][3] *= sc1;
        }

        #pragma unroll
        for (int kb = 0; kb < 4; kb++) {
            uint32_t a[4];
            a[0] = pack_bf16(s[2*kb  ][0], s[2*kb  ][1]);
            a[1] = pack_bf16(s[2*kb  ][2], s[2*kb  ][3]);
            a[2] = pack_bf16(s[2*kb+1][0], s[2*kb+1][1]);
            a[3] = pack_bf16(s[2*kb+1][2], s[2*kb+1][3]);
            #pragma unroll
            for (int j = 0; j < 8; j++) {
                uint32_t bf[2];
                ldmatrix_x2t(bf, &Vs[(st*64 + kb*16 + l15)*APB + j*8]);
                mma_bf16(o[j], a, bf);
            }
        }
        __syncthreads();
    }

    const float inv0 = 1.f / rowl0, inv1 = 1.f / rowl1;
    const int r0 = q0 + mb + qr, r1 = r0 + 8;
    #pragma unroll
    for (int j = 0; j < 8; j++) {
        const int col = h * DK + j * 8 + 2 * qc;
        *(uint32_t*)(O + ((size_t)b * SEQ + r0) * DIM + col) =
            pack_bf16(o[j][0] * inv0, o[j][1] * inv0);
        *(uint32_t*)(O + ((size_t)b * SEQ + r1) * DIM + col) =
            pack_bf16(o[j][2] * inv1, o[j][3] * inv1);
    }
}

// ---------------- LayerNorm kernels --------------------------------------------
// LN1 apply -> bf16 only (reads mean/rstd produced by Wo GEMM's last block)
__global__ void ln_apply_bf16_kernel(const float* __restrict__ X,
                                     const float* __restrict__ gamma, const float* __restrict__ beta,
                                     const float* __restrict__ mean, const float* __restrict__ rstd,
                                     __nv_bfloat16* __restrict__ Yb)
{
    const float4* x4 = (const float4*)X;
    const float4* g4 = (const float4*)gamma;
    const float4* b4 = (const float4*)beta;
    const int total = BATCH * (SD/4);
    for (int idx = blockIdx.x * blockDim.x + threadIdx.x; idx < total;
         idx += gridDim.x * blockDim.x) {
        const int b   = idx >> 16;
        const int loc = idx & 65535;
        const float m = mean[b], r = rstd[b];
        float4 v = x4[idx], g = g4[loc], be = b4[loc];
        uint2 p;
        p.x = pack_bf16((v.x - m) * r * g.x + be.x, (v.y - m) * r * g.y + be.y);
        p.y = pack_bf16((v.z - m) * r * g.z + be.z, (v.w - m) * r * g.w + be.w);
        ((uint2*)Yb)[idx] = p;
    }
}

// stats of y2 = LN2(z) on the fly; last block reduces 64 partials -> mean3/rstd3
__global__ void ln_stats_y2_kernel(const float* __restrict__ Z,
                                   const float* __restrict__ gamma, const float* __restrict__ beta,
                                   const float* __restrict__ mean2, const float* __restrict__ rstd2,
                                   float* __restrict__ psum, float* __restrict__ psq,
                                   int* __restrict__ fctr, float* __restrict__ mean3,
                                   float* __restrict__ rstd3)
{
    const int b = blockIdx.y, chunk = blockIdx.x;
    __shared__ int s_last;
    const size_t base = (size_t)b * SD + (size_t)chunk * 4096;
    const float4* z4 = (const float4*)(Z + base);
    const float4* g4 = (const float4*)(gamma + (size_t)chunk * 4096);
    const float4* b4 = (const float4*)(beta  + (size_t)chunk * 4096);
    const float m = mean2[b], r = rstd2[b];
    float s = 0.f, q = 0.f;
    #pragma unroll
    for (int i = 0; i < 4; i++) {
        const int t = threadIdx.x + 256*i;
        float4 v = z4[t], g = g4[t], be = b4[t];
        float4 y;
        y.x = (v.x - m) * r * g.x + be.x;
        y.y = (v.y - m) * r * g.y + be.y;
        y.z = (v.z - m) * r * g.z + be.z;
        y.w = (v.w - m) * r * g.w + be.w;
        s += y.x + y.y + y.z + y.w;
        q += y.x*y.x + y.y*y.y + y.z*y.z + y.w*y.w;
    }
    #pragma unroll
    for (int off = 16; off; off >>= 1) {
        s += __shfl_down_sync(0xffffffffu, s, off);
        q += __shfl_down_sync(0xffffffffu, q, off);
    }
    __shared__ float ws[8], wq[8];
    if ((threadIdx.x & 31) == 0) { ws[threadIdx.x >> 5] = s; wq[threadIdx.x >> 5] = q; }
    __syncthreads();
    if (threadIdx.x == 0) {
        float S = 0.f, Q = 0.f;
        #pragma unroll
        for (int w = 0; w < 8; w++) { S += ws[w]; Q += wq[w]; }
        psum[b*64 + chunk] = S;
        psq [b*64 + chunk] = Q;
        __threadfence();
        const int prev = atomicAdd(fctr, 1);
        s_last = (prev == (int)(gridDim.x * gridDim.y) - 1);
    }
    __syncthreads();
    if (s_last && threadIdx.x < BATCH) {
        float S = 0.f, Q = 0.f;
        #pragma unroll
        for (int t = 0; t < 64; t++) { S += psum[threadIdx.x*64 + t]; Q += psq[threadIdx.x*64 + t]; }
        const float m3 = S / (float)SD;
        mean3[threadIdx.x] = m3;
        rstd3[threadIdx.x] = rsqrtf(Q / (float)SD - m3 * m3 + LN_EPS);
    }
}

// out = LN3( LN2(z) ), both applied on the fly from z
__global__ void ln_apply_y2_kernel(const float* __restrict__ Z,
                                   const float* __restrict__ gamma, const float* __restrict__ beta,
                                   const float* __restrict__ mean2, const float* __restrict__ rstd2,
                                   const float* __restrict__ mean3, const float* __restrict__ rstd3,
                                   float* __restrict__ out)
{
    const float4* z4 = (const float4*)Z;
    const float4* g4 = (const float4*)gamma;
    const float4* b4 = (const float4*)beta;
    float4* o4 = (float4*)out;
    const int total = BATCH * (SD/4);
    for (int idx = blockIdx.x * blockDim.x + threadIdx.x; idx < total;
         idx += gridDim.x * blockDim.x) {
        const int b   = idx >> 16;
        const int loc = idx & 65535;
        const float m2 = mean2[b], r2 = rstd2[b];
        const float m3 = mean3[b], r3 = rstd3[b];
        float4 v = z4[idx], g = g4[loc], be = b4[loc];
        float4 y, o;
        y.x = (v.x - m2) * r2 * g.x + be.x;
        y.y = (v.y - m2) * r2 * g.y + be.y;
        y.z = (v.z - m2) * r2 * g.z + be.z;
        y.w = (v.w - m2) * r2 * g.w + be.w;
        o.x = (y.x - m3) * r3 * g.x + be.x;
        o.y = (y.y - m3) * r3 * g.y + be.y;
        o.z = (y.z - m3) * r3 * g.z + be.z;
        o.w = (y.w - m3) * r3 * g.w + be.w;
        o4[idx] = o;
    }
}

// ---------------- launch ------------------------------------------------------
#define ATTN_SMEM ((128*APB + 4*64*APB) * 2)   // 55296 bytes

extern "C" void kernel_launch(void* const* d_in, const int* in_sizes, int n_in,
                              void* d_out, int out_size)
{
    const float* x     = (const float*)d_in[0];
    const float* Wq    = (const float*)d_in[1];
    const float* bq    = (const float*)d_in[2];
    const float* Wk    = (const float*)d_in[3];
    const float* bk    = (const float*)d_in[4];
    const float* Wv    = (const float*)d_in[5];
    const float* bv    = (const float*)d_in[6];
    const float* Wo    = (const float*)d_in[7];
    const float* bo    = (const float*)d_in[8];
    const float* W1    = (const float*)d_in[9];
    const float* b1    = (const float*)d_in[10];
    const float* W2    = (const float*)d_in[11];
    const float* b2    = (const float*)d_in[12];
    const float* W3    = (const float*)d_in[13];
    const float* b3    = (const float*)d_in[14];
    const float* gamma = (const float*)d_in[15];
    const float* beta  = (const float*)d_in[16];
    float* out = (float*)d_out;

    float *y0_, *z_, *psum_, *psq_, *mean_, *rstd_, *bqkv_;
    int* ctr_;
    cudaGetSymbolAddress((void**)&y0_, g_y0);
    cudaGetSymbolAddress((void**)&z_,  g_z);
    cudaGetSymbolAddress((void**)&psum_, g_psum);
    cudaGetSymbolAddress((void**)&psq_,  g_psq);
    cudaGetSymbolAddress((void**)&mean_, g_mean);
    cudaGetSymbolAddress((void**)&rstd_, g_rstd);
    cudaGetSymbolAddress((void**)&bqkv_, g_bqkv);
    cudaGetSymbolAddress((void**)&ctr_,  g_ctr);

    __nv_bfloat16 *xb, *qb, *kb, *vb, *ccb, *y1b, *f1b, *f2b;
    __nv_bfloat16 *wqkvb, *wob, *w1b, *w2b, *w3b;
    cudaGetSymbolAddress((void**)&xb,    gb_x);
    cudaGetSymbolAddress((void**)&qb,    gb_q);
    cudaGetSymbolAddress((void**)&kb,    gb_k);
    cudaGetSymbolAddress((void**)&vb,    gb_v);
    cudaGetSymbolAddress((void**)&ccb,   gb_cc);
    cudaGetSymbolAddress((void**)&y1b,   gb_y1);
    cudaGetSymbolAddress((void**)&f1b,   gb_f1);
    cudaGetSymbolAddress((void**)&f2b,   gb_f2);
    cudaGetSymbolAddress((void**)&wqkvb, gb_wqkv);
    cudaGetSymbolAddress((void**)&wob,   gb_wo);
    cudaGetSymbolAddress((void**)&w1b,   gb_w1);
    cudaGetSymbolAddress((void**)&w2b,   gb_w2);
    cudaGetSymbolAddress((void**)&w3b,   gb_w3);

    float* mean1_ = mean_;            float* rstd1_ = rstd_;
    float* mean2_ = mean_ + BATCH;    float* rstd2_ = rstd_ + BATCH;
    float* mean3_ = mean_ + 2*BATCH;  float* rstd3_ = rstd_ + 2*BATCH;

    cudaFuncSetAttribute(attn_bf16_kernel,
                         cudaFuncAttributeMaxDynamicSharedMemorySize, ATTN_SMEM);

    // converts + bias build + counter reset in ONE launch
    CvtArgs ca;
    ca.seg[0] = { x,  xb,                  (MTOT*DIM)/4, 1.f    };
    ca.seg[1] = { Wq, wqkvb,               (DIM*DIM)/4,  QSCALE };
    ca.seg[2] = { Wk, wqkvb + DIM*DIM,     (DIM*DIM)/4,  1.f    };
    ca.seg[3] = { Wv, wqkvb + 2*DIM*DIM,   (DIM*DIM)/4,  1.f    };
    ca.seg[4] = { Wo, wob,                 (DIM*DIM)/4,  1.f    };
    ca.seg[5] = { W1, w1b,                 (FF*DIM)/4,   1.f    };
    ca.seg[6] = { W2, w2b,                 (FF*FF)/4,    1.f    };
    ca.seg[7] = { W3, w3b,                 (DIM*FF)/4,   1.f    };
    cvt_multi<<<1024, 256>>>(ca, bq, bk, bv, bqkv_, ctr_);

    // fused QKV projection
    gemm_qkv_kernel<<<dim3(12, 128), 256>>>(xb, wqkvb, bqkv_, qb, kb, vb);

    // attention (128 q-rows per block)
    attn_bf16_kernel<<<dim3(SEQ/128, BATCH*HEADS), 256, ATTN_SMEM>>>(qb, kb, vb, ccb);

    // output projection + residual(x) -> y0; LN1 stats + last-block final -> mean1/rstd1
    gemm_bf16_kernel<<<dim3(4, 128), 256>>>(ccb, wob, bo, x, y0_, nullptr,
                                            MTOT, DIM, DIM, 0, psum_, psq_,
                                            nullptr, nullptr, nullptr, nullptr, nullptr,
                                            ctr_ + 0, mean1_, rstd1_);

    // LN1 apply -> y1b (bf16 only)
    ln_apply_bf16_kernel<<<2048, 256>>>(y0_, gamma, beta, mean1_, rstd1_, y1b);

    // FFN
    gemm_bf16_kernel<<<dim3(2, 128), 256>>>(y1b, w1b, b1, nullptr, nullptr, f1b,
                                            MTOT, FF, DIM, 1, nullptr, nullptr,
                                            nullptr, nullptr, nullptr, nullptr, nullptr,
                                            nullptr, nullptr, nullptr);
    gemm_bf16_kernel<<<dim3(2, 128), 256>>>(f1b, w2b, b2, nullptr, nullptr, f2b,
                                            MTOT, FF, FF, 1, nullptr, nullptr,
                                            nullptr, nullptr, nullptr, nullptr, nullptr,
                                            nullptr, nullptr, nullptr);
    // W3: y1 recomputed on the fly from y0 + LN1; LN2 stats + final -> mean2/rstd2
    gemm_bf16_kernel<<<dim3(4, 128), 256>>>(f2b, w3b, b3, nullptr, z_, nullptr,
                                            MTOT, DIM, FF, 0, psum_, psq_,
                                            y0_, gamma, beta, mean1_, rstd1_,
                                            ctr_ + 1, mean2_, rstd2_);

    // y2 stats on the fly (+ last-block final -> mean3/rstd3)
    ln_stats_y2_kernel<<<dim3(64, BATCH), 256>>>(z_, gamma, beta, mean2_, rstd2_,
                                                 psum_, psq_, ctr_ + 2, mean3_, rstd3_);

    // final double-apply -> out
    ln_apply_y2_kernel<<<2048, 256>>>(z_, gamma, beta, mean2_, rstd2_, mean3_, rstd3_, out);
}

// round 16
// speedup vs baseline: 1.1055x; 1.0387x over previous
#include <cuda_runtime.h>
#include <cuda_bf16.h>
#include <cstdint>
#include <cstdio>

// Problem constants
#define BATCH 32
#define SEQ   512
#define DIM   512
#define HEADS 8
#define DK    64
#define FF    200
#define MTOT  (BATCH*SEQ)        // 16384
#define SD    (SEQ*DIM)          // 262144
#define QKN   (3*DIM)            // 1536 fused QKV width
#define LN_EPS 1e-5f
#define QSCALE (0.125f * 1.44269504088896340736f)   // 1/8 * log2(e)

// ---------------- scratch (device globals; no allocation allowed) -------------
__device__ float g_y0[MTOT*DIM];
__device__ float g_z [MTOT*DIM];
__device__ float g_psum[BATCH*64];
__device__ float g_psq [BATCH*64];
__device__ float g_mean[3*BATCH];
__device__ float g_rstd[3*BATCH];
__device__ float g_bqkv[QKN];

__device__ __nv_bfloat16 gb_x [MTOT*DIM];
__device__ __nv_bfloat16 gb_q [MTOT*DIM];
__device__ __nv_bfloat16 gb_k [MTOT*DIM];
__device__ __nv_bfloat16 gb_v [MTOT*DIM];
__device__ __nv_bfloat16 gb_cc[MTOT*DIM];
__device__ __nv_bfloat16 gb_y1[MTOT*DIM];
__device__ __nv_bfloat16 gb_f1[MTOT*FF];
__device__ __nv_bfloat16 gb_f2[MTOT*FF];
__device__ __nv_bfloat16 gb_wqkv[QKN*DIM];
__device__ __nv_bfloat16 gb_wo[DIM*DIM];
__device__ __nv_bfloat16 gb_w1[FF*DIM];
__device__ __nv_bfloat16 gb_w2[FF*FF];
__device__ __nv_bfloat16 gb_w3[DIM*FF];

// ---------------- helpers ------------------------------------------------------
__device__ __forceinline__ uint32_t pack_bf16(float a, float b) {
    __nv_bfloat162 h = __floats2bfloat162_rn(a, b);
    return *(uint32_t*)&h;
}

__device__ __forceinline__ float fexp2(float x) {
    float y;
    asm("ex2.approx.ftz.f32 %0, %1;" : "=f"(y) : "f"(x));
    return y;
}

__device__ __forceinline__ void mma_bf16(float* c, const uint32_t* a, const uint32_t* b) {
    asm volatile(
        "mma.sync.aligned.m16n8k16.row.col.f32.bf16.bf16.f32 "
        "{%0,%1,%2,%3}, {%4,%5,%6,%7}, {%8,%9}, {%0,%1,%2,%3};\n"
        : "+f"(c[0]), "+f"(c[1]), "+f"(c[2]), "+f"(c[3])
        : "r"(a[0]), "r"(a[1]), "r"(a[2]), "r"(a[3]),
          "r"(b[0]), "r"(b[1]));
}

__device__ __forceinline__ void ldmatrix_x4(uint32_t* r, const void* p) {
    uint32_t a = (uint32_t)__cvta_generic_to_shared(p);
    asm volatile("ldmatrix.sync.aligned.m8n8.x4.shared.b16 {%0,%1,%2,%3}, [%4];"
                 : "=r"(r[0]), "=r"(r[1]), "=r"(r[2]), "=r"(r[3]) : "r"(a));
}
__device__ __forceinline__ void ldmatrix_x2(uint32_t* r, const void* p) {
    uint32_t a = (uint32_t)__cvta_generic_to_shared(p);
    asm volatile("ldmatrix.sync.aligned.m8n8.x2.shared.b16 {%0,%1}, [%2];"
                 : "=r"(r[0]), "=r"(r[1]) : "r"(a));
}
__device__ __forceinline__ void ldmatrix_x2t(uint32_t* r, const void* p) {
    uint32_t a = (uint32_t)__cvta_generic_to_shared(p);
    asm volatile("ldmatrix.sync.aligned.m8n8.x2.trans.shared.b16 {%0,%1}, [%2];"
                 : "=r"(r[0]), "=r"(r[1]) : "r"(a));
}

__device__ __forceinline__ void cp_async16(void* smem, const void* gmem, bool valid) {
    uint32_t s = (uint32_t)__cvta_generic_to_shared(smem);
    int sz = valid ? 16 : 0;
    asm volatile("cp.async.cg.shared.global [%0], [%1], 16, %2;"
                 :: "r"(s), "l"(gmem), "r"(sz));
}
__device__ __forceinline__ void cp_commit() { asm volatile("cp.async.commit_group;"); }
__device__ __forceinline__ void cp_wait1()  { asm volatile("cp.async.wait_group 1;"); }

// ---------------- converts + bias build (single launch) ------------------------
struct CvtSeg  { const float* src; __nv_bfloat16* dst; int n4; float scale; };
struct CvtArgs { CvtSeg seg[8]; };

__global__ void cvt_multi(CvtArgs a, const float* __restrict__ bq,
                          const float* __restrict__ bk, const float* __restrict__ bv,
                          float* __restrict__ bqkv)
{
    const int gi = blockIdx.x * blockDim.x + threadIdx.x;
    if (gi < QKN) {
        float v;
        if (gi < DIM)        v = bq[gi] * QSCALE;
        else if (gi < 2*DIM) v = bk[gi - DIM];
        else                 v = bv[gi - 2*DIM];
        bqkv[gi] = v;
    }
    #pragma unroll
    for (int sg = 0; sg < 8; sg++) {
        const float* src = a.seg[sg].src;
        __nv_bfloat16* dst = a.seg[sg].dst;
        const int n4 = a.seg[sg].n4;
        const float sc = a.seg[sg].scale;
        for (int i = gi; i < n4; i += gridDim.x * blockDim.x) {
            float4 v = ((const float4*)src)[i];
            uint2 p;
            p.x = pack_bf16(v.x * sc, v.y * sc);
            p.y = pack_bf16(v.z * sc, v.w * sc);
            ((uint2*)dst)[i] = p;
        }
    }
}

// ---------------- BF16 GEMM: 128x128, BK=32, 2-stage cp.async ------------------
// optional fused LN partial stats; optional on-the-fly LN residual
#define GP 40
__global__ void __launch_bounds__(256)
gemm_bf16_kernel(const __nv_bfloat16* __restrict__ A, const __nv_bfloat16* __restrict__ B,
                 const float* __restrict__ bias, const float* __restrict__ res,
                 float* __restrict__ C, __nv_bfloat16* __restrict__ Cb,
                 int M, int N, int K, int relu,
                 float* __restrict__ psum, float* __restrict__ psq,
                 const float* __restrict__ lnx, const float* __restrict__ lngam,
                 const float* __restrict__ lnbet, const float* __restrict__ lnmean,
                 const float* __restrict__ lnrstd)
{
    __shared__ __nv_bfloat16 As[2][128][GP];
    __shared__ __nv_bfloat16 Bs[2][128][GP];
    __shared__ float sred[8], qred[8];

    const int tid  = threadIdx.x;
    const int wid  = tid >> 5;
    const int lane = tid & 31;
    const int wm   = wid >> 2;
    const int wn   = wid & 3;
    const int qr   = lane >> 2;
    const int qc   = lane & 3;
    const int m0   = blockIdx.y * 128;
    const int n0   = blockIdx.x * 128;

    const int lr  = tid >> 2;
    const int c8  = (tid & 3) * 8;

    const int l15 = lane & 15;
    const int a_co = (lane >> 4) << 3;
    const int l7  = lane & 7;
    const int b_co = ((lane >> 3) & 1) << 3;

    float acc[4][4][4];
    #pragma unroll
    for (int i = 0; i < 4; i++)
        #pragma unroll
        for (int j = 0; j < 4; j++)
            #pragma unroll
            for (int r = 0; r < 4; r++) acc[i][j][r] = 0.f;

    const int KT = (K + 31) >> 5;

    auto load_stage = [&](int st, int kt) {
        const int kc = kt * 32 + c8;
        const bool kok = (kc < K);
        #pragma unroll
        for (int half = 0; half < 2; half++) {
            const int r = lr + 64 * half;
            cp_async16(&As[st][r][c8], A + (size_t)(m0 + r) * K + kc, kok);
            const int n = n0 + r;
            cp_async16(&Bs[st][r][c8], B + (size_t)n * K + kc, kok && (n < N));
        }
    };

    load_stage(0, 0);
    cp_commit();

    for (int kt = 0; kt < KT; kt++) {
        if (kt + 1 < KT) load_stage((kt + 1) & 1, kt + 1);
        cp_commit();
        cp_wait1();
        __syncthreads();

        const int st = kt & 1;
        #pragma unroll
        for (int ks = 0; ks < 2; ks++) {
            uint32_t afr[4][4], bfr[4][2];
            #pragma unroll
            for (int i = 0; i < 4; i++)
                ldmatrix_x4(afr[i], &As[st][wm*64 + i*16 + l15][ks*16 + a_co]);
            #pragma unroll
            for (int j = 0; j < 4; j++)
                ldmatrix_x2(bfr[j], &Bs[st][wn*32 + j*8 + l7][ks*16 + b_co]);
            #pragma unroll
            for (int i = 0; i < 4; i++)
                #pragma unroll
                for (int j = 0; j < 4; j++)
                    mma_bf16(acc[i][j], afr[i], bfr[j]);
        }
        __syncthreads();
    }

    float ts = 0.f, tq = 0.f;
    #pragma unroll
    for (int i = 0; i < 4; i++) {
        const int row = m0 + wm * 64 + i * 16 + qr;
        #pragma unroll
        for (int j = 0; j < 4; j++) {
            const int col = n0 + wn * 32 + j * 8 + 2 * qc;
            if (col < N) {
                const float2 bi = *(const float2*)(bias + col);
                float v0 = acc[i][j][0] + bi.x;
                float v1 = acc[i][j][1] + bi.y;
                float v2 = acc[i][j][2] + bi.x;
                float v3 = acc[i][j][3] + bi.y;
                if (res) {
                    const float2 r0 = *(const float2*)(res + (size_t)row * N + col);
                    const float2 r1 = *(const float2*)(res + (size_t)(row + 8) * N + col);
                    v0 += r0.x; v1 += r0.y; v2 += r1.x; v3 += r1.y;
                }
                if (lnx) {
                    const int bidx = row >> 9;
                    const float m1 = lnmean[bidx], r1s = lnrstd[bidx];
                    const int sr0 = row & 511, sr1 = (row + 8) & 511;
                    const float2 x0 = *(const float2*)(lnx + (size_t)row * N + col);
                    const float2 x1 = *(const float2*)(lnx + (size_t)(row + 8) * N + col);
                    const float2 g0 = *(const float2*)(lngam + (size_t)sr0 * N + col);
                    const float2 e0 = *(const float2*)(lnbet + (size_t)sr0 * N + col);
                    const float2 g1 = *(const float2*)(lngam + (size_t)sr1 * N + col);
                    const float2 e1 = *(const float2*)(lnbet + (size_t)sr1 * N + col);
                    v0 += (x0.x - m1) * r1s * g0.x + e0.x;
                    v1 += (x0.y - m1) * r1s * g0.y + e0.y;
                    v2 += (x1.x - m1) * r1s * g1.x + e1.x;
                    v3 += (x1.y - m1) * r1s * g1.y + e1.y;
                }
                if (relu) {
                    v0 = fmaxf(v0, 0.f); v1 = fmaxf(v1, 0.f);
                    v2 = fmaxf(v2, 0.f); v3 = fmaxf(v3, 0.f);
                }
                if (C) {
                    *(float2*)(C + (size_t)row * N + col)       = make_float2(v0, v1);
                    *(float2*)(C + (size_t)(row + 8) * N + col) = make_float2(v2, v3);
                }
                if (Cb) {
                    *(uint32_t*)(Cb + (size_t)row * N + col)       = pack_bf16(v0, v1);
                    *(uint32_t*)(Cb + (size_t)(row + 8) * N + col) = pack_bf16(v2, v3);
                }
                if (psum) {
                    ts += v0 + v1 + v2 + v3;
                    tq += v0*v0 + v1*v1 + v2*v2 + v3*v3;
                }
            }
        }
    }

    if (psum) {
        #pragma unroll
        for (int off = 16; off; off >>= 1) {
            ts += __shfl_xor_sync(0xffffffffu, ts, off);
            tq += __shfl_xor_sync(0xffffffffu, tq, off);
        }
        if (lane == 0) { sred[wid] = ts; qred[wid] = tq; }
        __syncthreads();
        if (tid == 0) {
            float S = 0.f, Q = 0.f;
            #pragma unroll
            for (int w = 0; w < 8; w++) { S += sred[w]; Q += qred[w]; }
            const int slot = (blockIdx.y >> 2) * 16 + (blockIdx.y & 3) * 4 + blockIdx.x;
            psum[slot] = S;
            psq [slot] = Q;
        }
    }
}

// QKV GEMM: A[M,512] x Wqkv[1536,512]^T; epilogue splits cols into q/k/v buffers
__global__ void __launch_bounds__(256)
gemm_qkv_kernel(const __nv_bfloat16* __restrict__ A, const __nv_bfloat16* __restrict__ B,
                const float* __restrict__ bias,
                __nv_bfloat16* __restrict__ Qo, __nv_bfloat16* __restrict__ Ko,
                __nv_bfloat16* __restrict__ Vo)
{
    __shared__ __nv_bfloat16 As[2][128][GP];
    __shared__ __nv_bfloat16 Bs[2][128][GP];

    const int tid  = threadIdx.x;
    const int wid  = tid >> 5;
    const int lane = tid & 31;
    const int wm   = wid >> 2;
    const int wn   = wid & 3;
    const int qr   = lane >> 2;
    const int qc   = lane & 3;
    const int m0   = blockIdx.y * 128;
    const int n0   = blockIdx.x * 128;
    const int K    = DIM;

    const int lr  = tid >> 2;
    const int c8  = (tid & 3) * 8;

    const int l15 = lane & 15;
    const int a_co = (lane >> 4) << 3;
    const int l7  = lane & 7;
    const int b_co = ((lane >> 3) & 1) << 3;

    float acc[4][4][4];
    #pragma unroll
    for (int i = 0; i < 4; i++)
        #pragma unroll
        for (int j = 0; j < 4; j++)
            #pragma unroll
            for (int r = 0; r < 4; r++) acc[i][j][r] = 0.f;

    const int KT = K >> 5;

    auto load_stage = [&](int st, int kt) {
        const int kc = kt * 32 + c8;
        #pragma unroll
        for (int half = 0; half < 2; half++) {
            const int r = lr + 64 * half;
            cp_async16(&As[st][r][c8], A + (size_t)(m0 + r) * K + kc, true);
            cp_async16(&Bs[st][r][c8], B + (size_t)(n0 + r) * K + kc, true);
        }
    };

    load_stage(0, 0);
    cp_commit();

    for (int kt = 0; kt < KT; kt++) {
        if (kt + 1 < KT) load_stage((kt + 1) & 1, kt + 1);
        cp_commit();
        cp_wait1();
        __syncthreads();

        const int st = kt & 1;
        #pragma unroll
        for (int ks = 0; ks < 2; ks++) {
            uint32_t afr[4][4], bfr[4][2];
            #pragma unroll
            for (int i = 0; i < 4; i++)
                ldmatrix_x4(afr[i], &As[st][wm*64 + i*16 + l15][ks*16 + a_co]);
            #pragma unroll
            for (int j = 0; j < 4; j++)
                ldmatrix_x2(bfr[j], &Bs[st][wn*32 + j*8 + l7][ks*16 + b_co]);
            #pragma unroll
            for (int i = 0; i < 4; i++)
                #pragma unroll
                for (int j = 0; j < 4; j++)
                    mma_bf16(acc[i][j], afr[i], bfr[j]);
        }
        __syncthreads();
    }

    #pragma unroll
    for (int i = 0; i < 4; i++) {
        const int row = m0 + wm * 64 + i * 16 + qr;
        #pragma unroll
        for (int j = 0; j < 4; j++) {
            const int col = n0 + wn * 32 + j * 8 + 2 * qc;
            const float2 bi = *(const float2*)(bias + col);
            float v0 = acc[i][j][0] + bi.x;
            float v1 = acc[i][j][1] + bi.y;
            float v2 = acc[i][j][2] + bi.x;
            float v3 = acc[i][j][3] + bi.y;
            __nv_bfloat16* dst = (col < DIM) ? Qo : (col < 2*DIM ? Ko : Vo);
            const int lc = col & (DIM - 1);
            *(uint32_t*)(dst + (size_t)row * DIM + lc)       = pack_bf16(v0, v1);
            *(uint32_t*)(dst + (size_t)(row + 8) * DIM + lc) = pack_bf16(v2, v3);
        }
    }
}

// ---------------- BF16 flash attention (R10, unchanged) ------------------------
#define APB 72
__global__ void __launch_bounds__(256)
attn_bf16_kernel(const __nv_bfloat16* __restrict__ Q, const __nv_bfloat16* __restrict__ K,
                 const __nv_bfloat16* __restrict__ V, __nv_bfloat16* __restrict__ O)
{
    extern __shared__ __nv_bfloat16 smb[];
    __nv_bfloat16* Qs = smb;                   // [128][APB]
    __nv_bfloat16* Ks = smb + 128*APB;         // [2][64][APB]
    __nv_bfloat16* Vs = Ks + 2*64*APB;         // [2][64][APB]

    const int tid  = threadIdx.x;
    const int w    = tid >> 5;
    const int lane = tid & 31;
    const int qr   = lane >> 2;
    const int qc   = lane & 3;
    const int bh   = blockIdx.y;
    const int b    = bh >> 3, h = bh & 7;
    const int q0   = blockIdx.x * 128;
    const __nv_bfloat16* Qp = Q + ((size_t)b * SEQ + q0) * DIM + h * DK;
    const __nv_bfloat16* Kp = K + ((size_t)b * SEQ) * DIM + h * DK;
    const __nv_bfloat16* Vp = V + ((size_t)b * SEQ) * DIM + h * DK;
    const int mb = w * 16;

    const int l15 = lane & 15;
    const int a_co = (lane >> 4) << 3;
    const int l7  = lane & 7;
    const int b_co = ((lane >> 3) & 1) << 3;

    #pragma unroll
    for (int it = 0; it < 4; it++) {
        const int idx = tid + 256 * it;
        const int r = idx >> 3, cc8 = (idx & 7) * 8;
        *(uint4*)&Qs[r*APB + cc8] = *(const uint4*)(Qp + (size_t)r * DIM + cc8);
    }

    const int kvr = tid >> 2;
    const int kvc = (tid & 3) * 16;
    auto load_kv = [&](int st, int kt) {
        const int t0 = kt * 64;
        const size_t gofs = (size_t)(t0 + kvr) * DIM;
        __nv_bfloat16* kd = Ks + (st*64 + kvr)*APB;
        __nv_bfloat16* vd = Vs + (st*64 + kvr)*APB;
        cp_async16(kd + kvc,     Kp + gofs + kvc,     true);
        cp_async16(kd + kvc + 8, Kp + gofs + kvc + 8, true);
        cp_async16(vd + kvc,     Vp + gofs + kvc,     true);
        cp_async16(vd + kvc + 8, Vp + gofs + kvc + 8, true);
    };
    load_kv(0, 0); cp_commit();

    __syncthreads();
    uint32_t qf[4][4];
    #pragma unroll
    for (int ks = 0; ks < 4; ks++)
        ldmatrix_x4(qf[ks], &Qs[(mb + l15)*APB + ks*16 + a_co]);

    float o[8][4];
    #pragma unroll
    for (int j = 0; j < 8; j++)
        #pragma unroll
        for (int r = 0; r < 4; r++) o[j][r] = 0.f;
    float rowm0 = -1e30f, rowm1 = -1e30f, rowl0 = 0.f, rowl1 = 0.f;

    const int NT = SEQ / 64;
    for (int kt = 0; kt < NT; kt++) {
        if (kt + 1 < NT) load_kv((kt + 1) & 1, kt + 1);
        cp_commit();
        cp_wait1();
        __syncthreads();
        const int st = kt & 1;

        float s[8][4];
        #pragma unroll
        for (int j = 0; j < 8; j++)
            #pragma unroll
            for (int r = 0; r < 4; r++) s[j][r] = 0.f;
        #pragma unroll
        for (int ks = 0; ks < 4; ks++) {
            #pragma unroll
            for (int j = 0; j < 8; j++) {
                uint32_t bf[2];
                ldmatrix_x2(bf, &Ks[(st*64 + j*8 + l7)*APB + ks*16 + b_co]);
                mma_bf16(s[j], qf[ks], bf);
            }
        }

        float mt0 = -1e30f, mt1 = -1e30f;
        #pragma unroll
        for (int j = 0; j < 8; j++) {
            mt0 = fmaxf(mt0, fmaxf(s[j][0], s[j][1]));
            mt1 = fmaxf(mt1, fmaxf(s[j][2], s[j][3]));
        }
        mt0 = fmaxf(mt0, __shfl_xor_sync(0xffffffffu, mt0, 1));
        mt0 = fmaxf(mt0, __shfl_xor_sync(0xffffffffu, mt0, 2));
        mt1 = fmaxf(mt1, __shfl_xor_sync(0xffffffffu, mt1, 1));
        mt1 = fmaxf(mt1, __shfl_xor_sync(0xffffffffu, mt1, 2));

        const float mn0 = fmaxf(rowm0, mt0), mn1 = fmaxf(rowm1, mt1);
        const float sc0 = fexp2(rowm0 - mn0), sc1 = fexp2(rowm1 - mn1);
        rowm0 = mn0; rowm1 = mn1;

        float ps0 = 0.f, ps1 = 0.f;
        #pragma unroll
        for (int j = 0; j < 8; j++) {
            s[j][0] = fexp2(s[j][0] - mn0);
            s[j][1] = fexp2(s[j][1] - mn0);
            s[j][2] = fexp2(s[j][2] - mn1);
            s[j][3] = fexp2(s[j][3] - mn1);
            ps0 += s[j][0] + s[j][1];
            ps1 += s[j][2] + s[j][3];
        }
        ps0 += __shfl_xor_sync(0xffffffffu, ps0, 1);
        ps0 += __shfl_xor_sync(0xffffffffu, ps0, 2);
        ps1 += __shfl_xor_sync(0xffffffffu, ps1, 1);
        ps1 += __shfl_xor_sync(0xffffffffu, ps1, 2);
        rowl0 = rowl0 * sc0 + ps0;
        rowl1 = rowl1 * sc1 + ps1;

        #pragma unroll
        for (int j = 0; j < 8; j++) {
            o[j][0] *= sc0; o[j][1] *= sc0;
            o[j][2] *= sc1; o[j][3] *= sc1;
        }

        #pragma unroll
        for (int kb = 0; kb < 4; kb++) {
            uint32_t a[4];
            a[0] = pack_bf16(s[2*kb  ][0], s[2*kb  ][1]);
            a[1] = pack_bf16(s[2*kb  ][2], s[2*kb  ][3]);
            a[2] = pack_bf16(s[2*kb+1][0], s[2*kb+1][1]);
            a[3] = pack_bf16(s[2*kb+1][2], s[2*kb+1][3]);
            #pragma unroll
            for (int j = 0; j < 8; j++) {
                uint32_t bf[2];
                ldmatrix_x2t(bf, &Vs[(st*64 + kb*16 + l15)*APB + j*8]);
                mma_bf16(o[j], a, bf);
            }
        }
        __syncthreads();
    }

    const float inv0 = 1.f / rowl0, inv1 = 1.f / rowl1;
    const int r0 = q0 + mb + qr, r1 = r0 + 8;
    #pragma unroll
    for (int j = 0; j < 8; j++) {
        const int col = h * DK + j * 8 + 2 * qc;
        *(uint32_t*)(O + ((size_t)b * SEQ + r0) * DIM + col) =
            pack_bf16(o[j][0] * inv0, o[j][1] * inv0);
        *(uint32_t*)(O + ((size_t)b * SEQ + r1) * DIM + col) =
            pack_bf16(o[j][2] * inv1, o[j][3] * inv1);
    }
}

// ---------------- LayerNorm helpers (R10, unchanged) ---------------------------
__global__ void ln_final_kernel(const float* __restrict__ psum, const float* __restrict__ psq,
                                float* __restrict__ mean, float* __restrict__ rstd)
{
    const int b = blockIdx.x;
    float s = psum[b*64 + threadIdx.x];
    float q = psq [b*64 + threadIdx.x];
    #pragma unroll
    for (int off = 16; off; off >>= 1) {
        s += __shfl_down_sync(0xffffffffu, s, off);
        q += __shfl_down_sync(0xffffffffu, q, off);
    }
    __shared__ float ws[2], wq[2];
    if ((threadIdx.x & 31) == 0) { ws[threadIdx.x >> 5] = s; wq[threadIdx.x >> 5] = q; }
    __syncthreads();
    if (threadIdx.x == 0) {
        float S = ws[0] + ws[1], Q = wq[0] + wq[1];
        float m = S / (float)SD;
        float v = Q / (float)SD - m * m;
        mean[b] = m;
        rstd[b] = rsqrtf(v + LN_EPS);
    }
}

__global__ void ln_final16_kernel(const float* __restrict__ psum, const float* __restrict__ psq,
                                  float* __restrict__ mean, float* __restrict__ rstd)
{
    const int b = blockIdx.x;
    const int l = threadIdx.x;
    float s = (l < 16) ? psum[b*16 + l] : 0.f;
    float q = (l < 16) ? psq [b*16 + l] : 0.f;
    #pragma unroll
    for (int off = 8; off; off >>= 1) {
        s += __shfl_down_sync(0xffffffffu, s, off);
        q += __shfl_down_sync(0xffffffffu, q, off);
    }
    if (l == 0) {
        float m = s / (float)SD;
        float v = q / (float)SD - m * m;
        mean[b] = m;
        rstd[b] = rsqrtf(v + LN_EPS);
    }
}

__global__ void ln_apply_bf16_kernel(const float* __restrict__ X,
                                     const float* __restrict__ gamma, const float* __restrict__ beta,
                                     const float* __restrict__ mean, const float* __restrict__ rstd,
                                     __nv_bfloat16* __restrict__ Yb)
{
    const float4* x4 = (const float4*)X;
    const float4* g4 = (const float4*)gamma;
    const float4* b4 = (const float4*)beta;
    const int total = BATCH * (SD/4);
    for (int idx = blockIdx.x * blockDim.x + threadIdx.x; idx < total;
         idx += gridDim.x * blockDim.x) {
        const int b   = idx >> 16;
        const int loc = idx & 65535;
        const float m = mean[b], r = rstd[b];
        float4 v = x4[idx], g = g4[loc], be = b4[loc];
        uint2 p;
        p.x = pack_bf16((v.x - m) * r * g.x + be.x, (v.y - m) * r * g.y + be.y);
        p.y = pack_bf16((v.z - m) * r * g.z + be.z, (v.w - m) * r * g.w + be.w);
        ((uint2*)Yb)[idx] = p;
    }
}

__global__ void ln_stats_y2_kernel(const float* __restrict__ Z,
                                   const float* __restrict__ gamma, const float* __restrict__ beta,
                                   const float* __restrict__ mean2, const float* __restrict__ rstd2,
                                   float* __restrict__ psum, float* __restrict__ psq)
{
    const int b = blockIdx.y, chunk = blockIdx.x;
    const size_t base = (size_t)b * SD + (size_t)chunk * 4096;
    const float4* z4 = (const float4*)(Z + base);
    const float4* g4 = (const float4*)(gamma + (size_t)chunk * 4096);
    const float4* b4 = (const float4*)(beta  + (size_t)chunk * 4096);
    const float m = mean2[b], r = rstd2[b];
    float s = 0.f, q = 0.f;
    #pragma unroll
    for (int i = 0; i < 4; i++) {
        const int t = threadIdx.x + 256*i;
        float4 v = z4[t], g = g4[t], be = b4[t];
        float4 y;
        y.x = (v.x - m) * r * g.x + be.x;
        y.y = (v.y - m) * r * g.y + be.y;
        y.z = (v.z - m) * r * g.z + be.z;
        y.w = (v.w - m) * r * g.w + be.w;
        s += y.x + y.y + y.z + y.w;
        q += y.x*y.x + y.y*y.y + y.z*y.z + y.w*y.w;
    }
    #pragma unroll
    for (int off = 16; off; off >>= 1) {
        s += __shfl_down_sync(0xffffffffu, s, off);
        q += __shfl_down_sync(0xffffffffu, q, off);
    }
    __shared__ float ws[8], wq[8];
    if ((threadIdx.x & 31) == 0) { ws[threadIdx.x >> 5] = s; wq[threadIdx.x >> 5] = q; }
    __syncthreads();
    if (threadIdx.x == 0) {
        float S = 0.f, Q = 0.f;
        #pragma unroll
        for (int w = 0; w < 8; w++) { S += ws[w]; Q += wq[w]; }
        psum[b*64 + chunk] = S;
        psq [b*64 + chunk] = Q;
    }
}

__global__ void ln_apply_y2_kernel(const float* __restrict__ Z,
                                   const float* __restrict__ gamma, const float* __restrict__ beta,
                                   const float* __restrict__ mean2, const float* __restrict__ rstd2,
                                   const float* __restrict__ mean3, const float* __restrict__ rstd3,
                                   float* __restrict__ out)
{
    const float4* z4 = (const float4*)Z;
    const float4* g4 = (const float4*)gamma;
    const float4* b4 = (const float4*)beta;
    float4* o4 = (float4*)out;
    const int total = BATCH * (SD/4);
    for (int idx = blockIdx.x * blockDim.x + threadIdx.x; idx < total;
         idx += gridDim.x * blockDim.x) {
        const int b   = idx >> 16;
        const int loc = idx & 65535;
        const float m2 = mean2[b], r2 = rstd2[b];
        const float m3 = mean3[b], r3 = rstd3[b];
        float4 v = z4[idx], g = g4[loc], be = b4[loc];
        float4 y, o;
        y.x = (v.x - m2) * r2 * g.x + be.x;
        y.y = (v.y - m2) * r2 * g.y + be.y;
        y.z = (v.z - m2) * r2 * g.z + be.z;
        y.w = (v.w - m2) * r2 * g.w + be.w;
        o.x = (y.x - m3) * r3 * g.x + be.x;
        o.y = (y.y - m3) * r3 * g.y + be.y;
        o.z = (y.z - m3) * r3 * g.z + be.z;
        o.w = (y.w - m3) * r3 * g.w + be.w;
        o4[idx] = o;
    }
}

// ---------------- launch ------------------------------------------------------
#define ATTN_SMEM ((128*APB + 4*64*APB) * 2)   // 55296 bytes
#define APPLY_GRID 1184                        // 148 SM x 8 CTAs, single wave

extern "C" void kernel_launch(void* const* d_in, const int* in_sizes, int n_in,
                              void* d_out, int out_size)
{
    const float* x     = (const float*)d_in[0];
    const float* Wq    = (const float*)d_in[1];
    const float* bq    = (const float*)d_in[2];
    const float* Wk    = (const float*)d_in[3];
    const float* bk    = (const float*)d_in[4];
    const float* Wv    = (const float*)d_in[5];
    const float* bv    = (const float*)d_in[6];
    const float* Wo    = (const float*)d_in[7];
    const float* bo    = (const float*)d_in[8];
    const float* W1    = (const float*)d_in[9];
    const float* b1    = (const float*)d_in[10];
    const float* W2    = (const float*)d_in[11];
    const float* b2    = (const float*)d_in[12];
    const float* W3    = (const float*)d_in[13];
    const float* b3    = (const float*)d_in[14];
    const float* gamma = (const float*)d_in[15];
    const float* beta  = (const float*)d_in[16];
    float* out = (float*)d_out;

    float *y0_, *z_, *psum_, *psq_, *mean_, *rstd_, *bqkv_;
    cudaGetSymbolAddress((void**)&y0_, g_y0);
    cudaGetSymbolAddress((void**)&z_,  g_z);
    cudaGetSymbolAddress((void**)&psum_, g_psum);
    cudaGetSymbolAddress((void**)&psq_,  g_psq);
    cudaGetSymbolAddress((void**)&mean_, g_mean);
    cudaGetSymbolAddress((void**)&rstd_, g_rstd);
    cudaGetSymbolAddress((void**)&bqkv_, g_bqkv);

    __nv_bfloat16 *xb, *qb, *kb, *vb, *ccb, *y1b, *f1b, *f2b;
    __nv_bfloat16 *wqkvb, *wob, *w1b, *w2b, *w3b;
    cudaGetSymbolAddress((void**)&xb,    gb_x);
    cudaGetSymbolAddress((void**)&qb,    gb_q);
    cudaGetSymbolAddress((void**)&kb,    gb_k);
    cudaGetSymbolAddress((void**)&vb,    gb_v);
    cudaGetSymbolAddress((void**)&ccb,   gb_cc);
    cudaGetSymbolAddress((void**)&y1b,   gb_y1);
    cudaGetSymbolAddress((void**)&f1b,   gb_f1);
    cudaGetSymbolAddress((void**)&f2b,   gb_f2);
    cudaGetSymbolAddress((void**)&wqkvb, gb_wqkv);
    cudaGetSymbolAddress((void**)&wob,   gb_wo);
    cudaGetSymbolAddress((void**)&w1b,   gb_w1);
    cudaGetSymbolAddress((void**)&w2b,   gb_w2);
    cudaGetSymbolAddress((void**)&w3b,   gb_w3);

    float* mean1_ = mean_;            float* rstd1_ = rstd_;
    float* mean2_ = mean_ + BATCH;    float* rstd2_ = rstd_ + BATCH;
    float* mean3_ = mean_ + 2*BATCH;  float* rstd3_ = rstd_ + 2*BATCH;

    cudaFuncSetAttribute(attn_bf16_kernel,
                         cudaFuncAttributeMaxDynamicSharedMemorySize, ATTN_SMEM);

    // converts + bias build in ONE launch; Wq pre-scaled by (1/8)*log2(e)
    CvtArgs ca;
    ca.seg[0] = { x,  xb,                  (MTOT*DIM)/4, 1.f    };
    ca.seg[1] = { Wq, wqkvb,               (DIM*DIM)/4,  QSCALE };
    ca.seg[2] = { Wk, wqkvb + DIM*DIM,     (DIM*DIM)/4,  1.f    };
    ca.seg[3] = { Wv, wqkvb + 2*DIM*DIM,   (DIM*DIM)/4,  1.f    };
    ca.seg[4] = { Wo, wob,                 (DIM*DIM)/4,  1.f    };
    ca.seg[5] = { W1, w1b,                 (FF*DIM)/4,   1.f    };
    ca.seg[6] = { W2, w2b,                 (FF*FF)/4,    1.f    };
    ca.seg[7] = { W3, w3b,                 (DIM*FF)/4,   1.f    };
    cvt_multi<<<1024, 256>>>(ca, bq, bk, bv, bqkv_);

    // fused QKV projection
    gemm_qkv_kernel<<<dim3(12, 128), 256>>>(xb, wqkvb, bqkv_, qb, kb, vb);

    // attention (128 q-rows per block)
    attn_bf16_kernel<<<dim3(SEQ/128, BATCH*HEADS), 256, ATTN_SMEM>>>(qb, kb, vb, ccb);

    // output projection + bias + residual(x) -> fp32 y0, fused LN1 partial stats
    gemm_bf16_kernel<<<dim3(4, 128), 256>>>(ccb, wob, bo, x, y0_, nullptr,
                                            MTOT, DIM, DIM, 0, psum_, psq_,
                                            nullptr, nullptr, nullptr, nullptr, nullptr);

    // LN1 -> y1b (bf16 only)
    ln_final16_kernel<<<BATCH, 32>>>(psum_, psq_, mean1_, rstd1_);
    ln_apply_bf16_kernel<<<APPLY_GRID, 256>>>(y0_, gamma, beta, mean1_, rstd1_, y1b);

    // FFN
    gemm_bf16_kernel<<<dim3(2, 128), 256>>>(y1b, w1b, b1, nullptr, nullptr, f1b,
                                            MTOT, FF, DIM, 1, nullptr, nullptr,
                                            nullptr, nullptr, nullptr, nullptr, nullptr);
    gemm_bf16_kernel<<<dim3(2, 128), 256>>>(f1b, w2b, b2, nullptr, nullptr, f2b,
                                            MTOT, FF, FF, 1, nullptr, nullptr,
                                            nullptr, nullptr, nullptr, nullptr, nullptr);
    // W3: residual y1 recomputed on the fly from y0 + LN1 params; fused LN2 stats
    gemm_bf16_kernel<<<dim3(4, 128), 256>>>(f2b, w3b, b3, nullptr, z_, nullptr,
                                            MTOT, DIM, FF, 0, psum_, psq_,
                                            y0_, gamma, beta, mean1_, rstd1_);

    // LN2 stats -> m2/r2; y2 stats on the fly -> m3/r3; fused double-apply -> out
    ln_final16_kernel<<<BATCH, 32>>>(psum_, psq_, mean2_, rstd2_);
    ln_stats_y2_kernel<<<dim3(64, BATCH), 256>>>(z_, gamma, beta, mean2_, rstd2_, psum_, psq_);
    ln_final_kernel<<<BATCH, 64>>>(psum_, psq_, mean3_, rstd3_);
    ln_apply_y2_kernel<<<APPLY_GRID, 256>>>(z_, gamma, beta, mean2_, rstd2_, mean3_, rstd3_, out);
}